// round 13
// baseline (speedup 1.0000x reference)
#include <cuda_runtime.h>
#include <cuda.h>
#include <cuda_bf16.h>
#include <math.h>
#include <stdint.h>

#define Bc 8
#define Nn 4096
#define Dd 768
#define Hh 12
#define dh 64
#define Mrows (Bc*Nn)      /* 32768 */
#define QKVC  (3*Dd)       /* 2304  */
#define GK    Dd           /* GEMM K = 768 */
#define NSPLIT 8

// ---------------- scratch (device globals; allocation-free rule) -----------
__device__ float g_qkv[(size_t)Mrows * QKVC];          // 302 MB
__device__ float g_attn[Bc*Hh*dh*dh];                  // 1.5 MB
__device__ float g_part[(size_t)Bc*Hh*NSPLIT*dh*dh];   // 12.6 MB
__device__ float g_psq[Bc*Hh*NSPLIT*2*dh];             // 0.4 MB
__device__ __align__(256) float g_xt[(size_t)Mrows*Dd];     // x rounded to tf32
__device__ __align__(256) float g_wt[(size_t)QKVC*Dd];      // Wqkv^T  [N,K] tf32
__device__ __align__(256) float g_wot[(size_t)Dd*Dd];       // Wout^T  [N,K] tf32
__device__ __align__(256) float g_oattn[(size_t)Mrows*Dd];  // v@attn  tf32
// tensormaps: [0]=x(A), [1]=WqkvT(B), [2]=oattn(A), [3]=WoutT(B)
__device__ __align__(128) CUtensorMap g_tmaps[4];

// ---------------- arch feature gate -----------------------------------------
#if defined(__CUDA_ARCH_FEAT_SM103_ALL) || defined(__CUDA_ARCH_FEAT_SM100_ALL) || defined(__CUDA_ARCH_FEAT_SM101_ALL)
#define HAS_TCG 1
#else
#define HAS_TCG 0
#endif

// ---------------- common helpers --------------------------------------------
__device__ __forceinline__ uint32_t smem_u32(const void* p){
    uint32_t a;
    asm("{ .reg .u64 t; cvta.to.shared.u64 t, %1; cvt.u32.u64 %0, t; }" : "=r"(a) : "l"(p));
    return a;
}
__device__ __forceinline__ float rna_tf32(float v){
    uint32_t u;
    asm("cvt.rna.tf32.f32 %0, %1;" : "=r"(u) : "f"(v));
    return __uint_as_float(u);
}

// ---------------- GEMM tile geometry ----------------------------------------
// MT=256 (2 TMEM D regions), NT=256, KCH=16 (64B rows, SW64), 6 stages of 32KB
#define MT 256
#define NT 256
#define KCH 16                  /* K elems per chunk: 16 fp32 = 64B rows */
#define NCH (GK/KCH)            /* 48 */
#define NSTAGE 6
#define CL 4                    /* cluster size: 4-way B multicast */
#define OA 0                    /* A tile 256x16 fp32 = 16KB (M halves +0/+8K) */
#define OB 16384                /* B tile 256x16 fp32 = 16KB (quarters +4K each) */
#define STAGE_BYTES 32768
#define SM_TILE0 1024
#define GEMM_SMEM (SM_TILE0 + NSTAGE*STAGE_BYTES) /* 197632 */

#if HAS_TCG
// ---------------- tcgen05 / TMA helpers (arch-specific pass only) -----------
__device__ __forceinline__ uint32_t elect1(){
    uint32_t p;
    asm volatile("{\n\t.reg .pred p;\n\telect.sync _|p, 0xFFFFFFFF;\n\tselp.b32 %0, 1, 0, p;\n\t}" : "=r"(p));
    return p;
}
__device__ __forceinline__ uint32_t ctarank(){
    uint32_t r;
    asm("mov.u32 %0, %%cluster_ctarank;" : "=r"(r));
    return r;
}
// SW64 descriptor: layout=4, version=1, SBO=32 (512B = 8 rows x 64B), LBO=1
static constexpr uint64_t DESC_BASE_SW64 =
    (uint64_t(4) << 61) | (uint64_t(1) << 46) | (uint64_t(32) << 32) | (uint64_t(1) << 16);
#define MK64(a) (DESC_BASE_SW64 | ((uint64_t)((a) >> 4) & 0x3FFF))
// idesc: F32 accum (1<<4), TF32 a/b (2<<7 | 2<<10), N=256 (32<<17), M=128 (8<<24)
#define GEMM_IDESC 0x8400910u

__device__ __forceinline__ void mma_tf32_ss(uint32_t d, uint64_t a, uint64_t b, uint32_t en){
    asm volatile(
        "{\n\t.reg .pred p;\n\tsetp.ne.u32 p, %3, 0;\n\t"
        "tcgen05.mma.cta_group::1.kind::tf32 [%0], %1, %2, %4, {%5,%5,%5,%5}, p;\n\t}"
        :: "r"(d), "l"(a), "l"(b), "r"(en), "r"(GEMM_IDESC), "r"(0u) : "memory");
}
__device__ __forceinline__ void tc_commit(uint32_t mbar){
    asm volatile("tcgen05.commit.cta_group::1.mbarrier::arrive::one.shared::cluster.b64 [%0];"
                 :: "r"(mbar) : "memory");
}
__device__ __forceinline__ void tc_commit_mc(uint32_t mbar, uint16_t mask){
    asm volatile("tcgen05.commit.cta_group::1.mbarrier::arrive::one.shared::cluster.multicast::cluster.b64 [%0], %1;"
                 :: "r"(mbar), "h"(mask) : "memory");
}
__device__ __forceinline__ void mbar_init(uint32_t mbar, uint32_t cnt){
    asm volatile("mbarrier.init.shared.b64 [%0], %1;" :: "r"(mbar), "r"(cnt) : "memory");
}
__device__ __forceinline__ void mbar_wait(uint32_t mbar, uint32_t parity){
    asm volatile(
        "{\n\t.reg .pred P;\n\tWL_%=:\n\t"
        "mbarrier.try_wait.parity.acquire.cta.shared::cta.b64 P, [%0], %1, 0x989680;\n\t"
        "@P bra.uni WD_%=;\n\tbra.uni WL_%=;\n\tWD_%=:\n\t}"
        :: "r"(mbar), "r"(parity) : "memory");
}
__device__ __forceinline__ void mbar_wait_rlx(uint32_t mbar, uint32_t parity){
    asm volatile(
        "{\n\t.reg .pred P;\n\tWL_%=:\n\t"
        "mbarrier.try_wait.parity.relaxed.cta.shared::cta.b64 P, [%0], %1, 0x989680;\n\t"
        "@P bra.uni WD_%=;\n\tbra.uni WL_%=;\n\tWD_%=:\n\t}"
        :: "r"(mbar), "r"(parity) : "memory");
}
#define EXPECT_TX(mbar, bytes) \
    asm volatile("mbarrier.arrive.expect_tx.shared.b64 _, [%0], %1;" \
                 :: "r"(mbar), "r"((uint32_t)(bytes)) : "memory")
#define TMA2D(smem, map, x, y, mbar) \
    asm volatile("cp.async.bulk.tensor.2d.shared::cta.global.tile.mbarrier::complete_tx::bytes " \
                 "[%0], [%1, {%2, %3}], [%4];" \
                 :: "r"((uint32_t)(smem)), "l"(map), "r"((int)(x)), "r"((int)(y)), \
                    "r"((uint32_t)(mbar)) : "memory")
#define TMA2D_MC(smem, map, x, y, mbar, mask) \
    asm volatile("cp.async.bulk.tensor.2d.shared::cluster.global.tile.mbarrier::complete_tx::bytes.multicast::cluster " \
                 "[%0], [%1, {%2, %3}], [%4], %5;" \
                 :: "r"((uint32_t)(smem)), "l"(map), "r"((int)(x)), "r"((int)(y)), \
                    "r"((uint32_t)(mbar)), "h"((uint16_t)(mask)) : "memory")
#define CLUSTER_SYNC() do { \
    asm volatile("barrier.cluster.arrive.aligned;" ::: "memory"); \
    asm volatile("barrier.cluster.wait.aligned;" ::: "memory"); \
} while(0)

#define TC_FENCE_AFTER()  asm volatile("tcgen05.fence::after_thread_sync;" ::: "memory")
#define TC_FENCE_BEFORE() asm volatile("tcgen05.fence::before_thread_sync;" ::: "memory")
#define TC_WAIT_LD() asm volatile("tcgen05.wait::ld.sync.aligned;" ::: "memory")

#define LDTM32(r, addr) \
    asm volatile( \
        "tcgen05.ld.sync.aligned.32x32b.x32.b32 " \
        "{%0, %1, %2, %3, %4, %5, %6, %7, " \
        " %8, %9, %10, %11, %12, %13, %14, %15, " \
        " %16, %17, %18, %19, %20, %21, %22, %23, " \
        " %24, %25, %26, %27, %28, %29, %30, %31}, [%32];" \
        : "=r"((r)[0]),  "=r"((r)[1]),  "=r"((r)[2]),  "=r"((r)[3]), \
          "=r"((r)[4]),  "=r"((r)[5]),  "=r"((r)[6]),  "=r"((r)[7]), \
          "=r"((r)[8]),  "=r"((r)[9]),  "=r"((r)[10]), "=r"((r)[11]), \
          "=r"((r)[12]), "=r"((r)[13]), "=r"((r)[14]), "=r"((r)[15]), \
          "=r"((r)[16]), "=r"((r)[17]), "=r"((r)[18]), "=r"((r)[19]), \
          "=r"((r)[20]), "=r"((r)[21]), "=r"((r)[22]), "=r"((r)[23]), \
          "=r"((r)[24]), "=r"((r)[25]), "=r"((r)[26]), "=r"((r)[27]), \
          "=r"((r)[28]), "=r"((r)[29]), "=r"((r)[30]), "=r"((r)[31]) \
        : "r"(addr))
#endif  // HAS_TCG

// smem control offsets
#define MB_FULL(s)  (8  + (s)*8)     /* full[s]:  data ready (count 1 + tx)   */
#define MB_EMPTY(s) (64 + (s)*8)     /* empty[s]: stage free (count CL)       */
#define MB_DONE     120              /* final MMA drain (count 1)             */

// ---------------------------------------------------------------------------
// Single-pass tf32 GEMM:  C[M,Ntot] = A[M,GK] * B^T  (B:[Ntot,GK] row-major)
// Cluster (1,4,1): 4 CTAs share the B tile; each loads a 64-row quarter and
// multicasts to all 4. 6-stage, KCH=16 pipeline; 2 TMEM D regions (M=256).
// ---------------------------------------------------------------------------
__global__ __launch_bounds__(256) __cluster_dims__(1, CL, 1)
void gemm_tf32(
    const CUtensorMap* __restrict__ tmaps,   // [A, B]
    const float* __restrict__ A, const float* __restrict__ B,
    float* __restrict__ C, int Ntot, const float* __restrict__ bias)
{
    const int tid = threadIdx.x;
    const int row0 = blockIdx.y * MT;
    const int col0 = blockIdx.x * NT;

#if HAS_TCG
    extern __shared__ char smem[];
    const uint32_t sbase = smem_u32(smem);
    const int wid = tid >> 5;
    const int lane = tid & 31;
    const uint32_t rank = ctarank();

    if (wid == 0) {
        asm volatile("tcgen05.alloc.cta_group::1.sync.aligned.shared::cta.b32 [%0], %1;"
                     :: "r"(sbase), "r"(512u) : "memory");
    }
    if (tid == 0) {
        #pragma unroll
        for (int s = 0; s < NSTAGE; s++) {
            mbar_init(sbase + MB_FULL(s), 1);    // producer's expect_tx arrival
            mbar_init(sbase + MB_EMPTY(s), CL);  // all 4 CTAs' MMA commits
        }
        mbar_init(sbase + MB_DONE, 1);
    }
    __syncthreads();
    uint32_t tmem;
    asm volatile("ld.shared.b32 %0, [%1];" : "=r"(tmem) : "r"(sbase));
    if (wid == 0)
        asm volatile("tcgen05.relinquish_alloc_permit.cta_group::1.sync.aligned;");

    // all mbarriers must be visible cluster-wide before any multicast TMA
    CLUSTER_SYNC();

    uint32_t leader = 0, producer = 0;
    if (wid == 0) leader = elect1();
    if (wid == 1) producer = elect1();

    if (producer) {
        for (int ch = 0; ch < NCH; ch++) {
            const int st = ch % NSTAGE;
            const uint32_t sb = sbase + SM_TILE0 + st*STAGE_BYTES;
            if (ch >= NSTAGE)
                mbar_wait_rlx(sbase + MB_EMPTY(st), ((ch - NSTAGE) / NSTAGE) & 1);
            EXPECT_TX(sbase + MB_FULL(st), 32768u);  // A 16KB + B 16KB (4 quarters)
            TMA2D(sb + OA, tmaps + 0, ch*KCH, row0, sbase + MB_FULL(st));
            TMA2D_MC(sb + OB + rank*4096, tmaps + 1, ch*KCH,
                     col0 + (int)rank*64, sbase + MB_FULL(st), 0xF);
        }
    }

    if (leader) {
        uint32_t first = 0;
        const uint32_t tm0 = tmem, tm1 = tmem + 256;
        for (int ch = 0; ch < NCH; ch++) {
            const int st = ch % NSTAGE;
            mbar_wait(sbase + MB_FULL(st), (ch / NSTAGE) & 1);
            const uint32_t sb = sbase + SM_TILE0 + st*STAGE_BYTES;
            const uint64_t dA0 = MK64(sb + OA);
            const uint64_t dA1 = MK64(sb + OA + 8192);
            const uint64_t dB  = MK64(sb + OB);
            mma_tf32_ss(tm0, dA0,     dB,     first);
            mma_tf32_ss(tm1, dA1,     dB,     first);
            first = 1;
            mma_tf32_ss(tm0, dA0 + 2, dB + 2, 1);    // second K=8 step (+32B)
            mma_tf32_ss(tm1, dA1 + 2, dB + 2, 1);
            tc_commit_mc(sbase + MB_EMPTY(st), 0xF); // arm all 4 CTAs' empty
        }
        tc_commit(sbase + MB_DONE);
    }

    // ---- all threads: wait for full MMA drain ----
    mbar_wait(sbase + MB_DONE, 0);
    TC_FENCE_AFTER();

    // ---- epilogue: warps 0-3 -> D0 rows, warps 4-7 -> D1 rows ----
    {
        const int mh = wid >> 2;
        const int r = row0 + mh*128 + (wid & 3)*32 + lane;
        const uint32_t tb = tmem + mh*256;
        float* crow = C + (size_t)r * Ntot;
        #pragma unroll
        for (int chk = 0; chk < 8; chk++) {
            uint32_t regs[32];
            LDTM32(regs, tb + chk*32);
            TC_WAIT_LD();
            const int c0 = col0 + chk*32;
            #pragma unroll
            for (int j = 0; j < 32; j += 4) {
                float4 v;
                v.x = __uint_as_float(regs[j+0]);
                v.y = __uint_as_float(regs[j+1]);
                v.z = __uint_as_float(regs[j+2]);
                v.w = __uint_as_float(regs[j+3]);
                if (bias) {
                    v.x += bias[c0+j+0]; v.y += bias[c0+j+1];
                    v.z += bias[c0+j+2]; v.w += bias[c0+j+3];
                }
                *(float4*)(crow + c0 + j) = v;
            }
        }
        TC_FENCE_BEFORE();
    }
    __syncthreads();
    // all peer multicast commits / TMAs must have landed before inval
    CLUSTER_SYNC();
    if (tid == 0) {
        #pragma unroll
        for (int s = 0; s < NSTAGE; s++) {
            asm volatile("mbarrier.inval.shared.b64 [%0];" :: "r"(sbase + MB_FULL(s)) : "memory");
            asm volatile("mbarrier.inval.shared.b64 [%0];" :: "r"(sbase + MB_EMPTY(s)) : "memory");
        }
        asm volatile("mbarrier.inval.shared.b64 [%0];" :: "r"(sbase + MB_DONE) : "memory");
    }
    __syncthreads();
    if (wid == 0) {
        asm volatile("tcgen05.dealloc.cta_group::1.sync.aligned.b32 %0, %1;"
                     :: "r"(tmem), "r"(512u));
    }
    CLUSTER_SYNC();

#else
    // ---- correctness-only fallback (dead code on sm_103a cubin) ----
    (void)tmaps;
    for (int idx = tid; idx < MT*NT; idx += 256) {
        const int r = row0 + idx / NT;
        const int c = col0 + idx % NT;
        float s = bias ? bias[c] : 0.f;
        for (int k = 0; k < GK; k++)
            s = fmaf(A[(size_t)r * GK + k], B[(size_t)c * GK + k], s);
        C[(size_t)r * Ntot + c] = s;
    }
#endif
}

// ---------------------------------------------------------------------------
// fp32 -> tf32-rounded fp32 (elementwise)
// ---------------------------------------------------------------------------
__global__ __launch_bounds__(256) void round_kernel(
    const float* __restrict__ in, float* __restrict__ outp, size_t n4)
{
    const size_t i = (size_t)blockIdx.x * blockDim.x + threadIdx.x;
    if (i >= n4) return;
    float4 v = ((const float4*)in)[i];
    v.x = rna_tf32(v.x); v.y = rna_tf32(v.y);
    v.z = rna_tf32(v.z); v.w = rna_tf32(v.w);
    ((float4*)outp)[i] = v;
}

// ---------------------------------------------------------------------------
// W [K,N] fp32 -> transposed tf32-rounded [N,K] row-major
// ---------------------------------------------------------------------------
__global__ __launch_bounds__(256) void transpose_round(
    const float* __restrict__ W, float* __restrict__ o, int K, int N)
{
    __shared__ float t[32][33];
    const int n0 = blockIdx.x * 32, k0 = blockIdx.y * 32;
    const int tx = threadIdx.x & 31, ty = threadIdx.x >> 5;
    #pragma unroll
    for (int i = ty; i < 32; i += 8)
        t[i][tx] = W[(size_t)(k0 + i) * N + n0 + tx];
    __syncthreads();
    #pragma unroll
    for (int i = ty; i < 32; i += 8)
        o[(size_t)(n0 + i) * K + k0 + tx] = rna_tf32(t[tx][i]);
}

// ---------------------------------------------------------------------------
// attn part 1: raw cross-cov partials + ssq partials over an N-slice of 512.
// ---------------------------------------------------------------------------
__global__ __launch_bounds__(256) void attn_part(void)
{
    const int bh = blockIdx.x;
    const int sl = blockIdx.y;
    const int b  = bh / Hh, h = bh % Hh;
    const int tid = threadIdx.x;
    const int tx = tid & 15, ty = tid >> 4;

    __shared__ float Qs[64][68];
    __shared__ float Ks[64][68];
    __shared__ float ps[256];

    const size_t rowbase = (size_t)b * Nn + sl * (Nn / NSPLIT);
    const int qoff = h * dh;
    const int koff = Dd + h * dh;

    float acc[4][4];
    #pragma unroll
    for (int i = 0; i < 4; i++)
        #pragma unroll
        for (int j = 0; j < 4; j++) acc[i][j] = 0.f;
    float pssq = 0.f;

    const int lr = tid >> 4;
    const int lc = (tid & 15) << 2;
    const int scol  = tid & 127;
    const int shalf = (tid >> 7) * 32;

    for (int n0 = 0; n0 < Nn / NSPLIT; n0 += 64) {
        #pragma unroll
        for (int pp = 0; pp < 64; pp += 16) {
            const size_t grow = (rowbase + n0 + pp + lr) * QKVC;
            *(float4*)&Qs[pp + lr][lc] = *(const float4*)(g_qkv + grow + qoff + lc);
            *(float4*)&Ks[pp + lr][lc] = *(const float4*)(g_qkv + grow + koff + lc);
        }
        __syncthreads();
        #pragma unroll 4
        for (int n = 0; n < 64; n++) {
            float rq[4], rk[4];
            *(float4*)rq = *(const float4*)&Qs[n][tx * 4];
            *(float4*)rk = *(const float4*)&Ks[n][ty * 4];
            #pragma unroll
            for (int i = 0; i < 4; i++)
                #pragma unroll
                for (int j = 0; j < 4; j++)
                    acc[i][j] = fmaf(rk[i], rq[j], acc[i][j]);
        }
        {
            const float* colp = (scol < 64) ? &Qs[0][scol] : &Ks[0][scol - 64];
            #pragma unroll
            for (int n = 0; n < 32; n++) {
                const float v = colp[(size_t)(shalf + n) * 68];
                pssq = fmaf(v, v, pssq);
            }
        }
        __syncthreads();
    }

    ps[tid] = pssq;
    __syncthreads();
    if (tid < 128)
        g_psq[(bh * NSPLIT + sl) * 128 + tid] = ps[tid] + ps[tid + 128];

    float* op = g_part + (size_t)(bh * NSPLIT + sl) * 4096;
    #pragma unroll
    for (int i = 0; i < 4; i++)
        #pragma unroll
        for (int j = 0; j < 4; j++)
            op[(ty * 4 + i) * 64 + tx * 4 + j] = acc[i][j];
}

// ---------------------------------------------------------------------------
// attn part 2: reduce partials, norms, temperature, softmax. grid 96.
// ---------------------------------------------------------------------------
__global__ __launch_bounds__(256) void attn_final(const float* __restrict__ temp)
{
    const int bh = blockIdx.x;
    const int h  = bh % Hh;
    const int tid = threadIdx.x;

    __shared__ float Qs[64][65];
    __shared__ float normQ[64], normK[64];

    if (tid < 128) {
        float s = 0.f;
        #pragma unroll
        for (int sl = 0; sl < NSPLIT; sl++)
            s += g_psq[(bh * NSPLIT + sl) * 128 + tid];
        const float nv = fmaxf(sqrtf(s), 1e-12f);
        if (tid < 64) normQ[tid] = nv; else normK[tid - 64] = nv;
    }
    __syncthreads();

    const float tv = temp[h];
    const float* pp = g_part + (size_t)bh * NSPLIT * 4096;
    #pragma unroll
    for (int e = 0; e < 16; e++) {
        const int idx = e * 256 + tid;
        float s = 0.f;
        #pragma unroll
        for (int sl = 0; sl < NSPLIT; sl++)
            s += pp[sl * 4096 + idx];
        const int p = idx >> 6, q = idx & 63;
        Qs[p][q] = s * tv / (normK[p] * normQ[q]);
    }
    __syncthreads();

    if (tid < 64) {
        const int p = tid;
        float m = -1e30f;
        for (int q = 0; q < 64; q++) m = fmaxf(m, Qs[p][q]);
        float s = 0.f;
        for (int q = 0; q < 64; q++) s += expf(Qs[p][q] - m);
        const float inv = 1.f / s;
        float* op = g_attn + (size_t)bh * 4096 + p * 64;
        for (int q = 0; q < 64; q++) op[q] = expf(Qs[p][q] - m) * inv;
    }
}

// ---------------------------------------------------------------------------
// out[b,h,n,q] = sum_p v[n,p] attn[p,q]  -> tf32-rounded fp32, row-major
// ---------------------------------------------------------------------------
__global__ __launch_bounds__(256) void av_kernel()
{
    const int bh = blockIdx.x;
    const int nt = blockIdx.y;
    const int b  = bh / Hh, h = bh % Hh;
    const int tid = threadIdx.x;
    const int tx = tid & 15, ty = tid >> 4;

    __shared__ float At[64][68];
    __shared__ float Vs[64][68];

    {
        const float* ap = g_attn + (size_t)bh * 4096;
        #pragma unroll
        for (int pp = 0; pp < 4; pp++) {
            const int idx = pp * 1024 + tid * 4;
            *(float4*)&At[idx >> 6][idx & 63] = *(const float4*)(ap + idx);
        }
    }
    const int lr = tid >> 4, lc = (tid & 15) << 2;
    const int voff = 2 * Dd + h * dh;
    const size_t rowbase = (size_t)b * Nn + nt * 64;
    #pragma unroll
    for (int pp = 0; pp < 64; pp += 16)
        *(float4*)&Vs[pp + lr][lc] =
            *(const float4*)(g_qkv + (rowbase + pp + lr) * QKVC + voff + lc);
    __syncthreads();

    float acc[4][4];
    #pragma unroll
    for (int i = 0; i < 4; i++)
        #pragma unroll
        for (int j = 0; j < 4; j++) acc[i][j] = 0.f;

    #pragma unroll 8
    for (int p = 0; p < 64; p++) {
        float ra[4];
        *(float4*)ra = *(const float4*)&At[p][tx * 4];
        float rv[4];
        #pragma unroll
        for (int i = 0; i < 4; i++) rv[i] = Vs[ty * 4 + i][p];
        #pragma unroll
        for (int i = 0; i < 4; i++)
            #pragma unroll
            for (int j = 0; j < 4; j++)
                acc[i][j] = fmaf(rv[i], ra[j], acc[i][j]);
    }

    #pragma unroll
    for (int i = 0; i < 4; i++) {
        const size_t r = rowbase + ty * 4 + i;
        float4 v;
        v.x = rna_tf32(acc[i][0]); v.y = rna_tf32(acc[i][1]);
        v.z = rna_tf32(acc[i][2]); v.w = rna_tf32(acc[i][3]);
        *(float4*)(g_oattn + r * Dd + h * dh + tx * 4) = v;
    }
}

// ---------------------------------------------------------------------------
// host: tensormap construction via driver entry point (no -lcuda needed)
// ---------------------------------------------------------------------------
typedef CUresult (*EncodeTiledFn)(
    CUtensorMap*, CUtensorMapDataType, cuuint32_t, void*,
    const cuuint64_t*, const cuuint64_t*, const cuuint32_t*, const cuuint32_t*,
    CUtensorMapInterleave, CUtensorMapSwizzle, CUtensorMapL2promotion,
    CUtensorMapFloatOOBfill);

static void encode_map(EncodeTiledFn enc, CUtensorMap* m, void* base,
                       unsigned long long nrows, unsigned boxrows)
{
    cuuint64_t dims[2]    = {(cuuint64_t)GK, nrows};   // [768 elems, nrows]
    cuuint64_t strides[1] = {(cuuint64_t)GK * 4};      // 3072 bytes per row
    cuuint32_t box[2]     = {16u, boxrows};            // 64B x boxrows
    cuuint32_t estr[2]    = {1u, 1u};
    enc(m, CU_TENSOR_MAP_DATA_TYPE_FLOAT32, 2, base, dims, strides, box, estr,
        CU_TENSOR_MAP_INTERLEAVE_NONE, CU_TENSOR_MAP_SWIZZLE_64B,
        CU_TENSOR_MAP_L2_PROMOTION_L2_128B, CU_TENSOR_MAP_FLOAT_OOB_FILL_NONE);
}

extern "C" void kernel_launch(void* const* d_in, const int* in_sizes, int n_in,
                              void* d_out, int out_size)
{
    const float* x     = (const float*)d_in[0];
    const float* Wqkv  = (const float*)d_in[1];
    const float* temp  = (const float*)d_in[2];
    const float* Wout  = (const float*)d_in[3];
    const float* bout  = (const float*)d_in[4];
    float* out = (float*)d_out;

    float *qkv, *xt, *wt, *wot, *oattn;
    cudaGetSymbolAddress((void**)&qkv,   g_qkv);
    cudaGetSymbolAddress((void**)&xt,    g_xt);
    cudaGetSymbolAddress((void**)&wt,    g_wt);
    cudaGetSymbolAddress((void**)&wot,   g_wot);
    cudaGetSymbolAddress((void**)&oattn, g_oattn);
    CUtensorMap* dmaps;
    cudaGetSymbolAddress((void**)&dmaps, g_tmaps);

    // build tensormaps (static host buffer persists for graph replays)
    static CUtensorMap h_tmaps[4];
    static EncodeTiledFn enc = nullptr;
    if (!enc) {
        void* p = nullptr;
        cudaDriverEntryPointQueryResult st;
        cudaGetDriverEntryPoint("cuTensorMapEncodeTiled", &p, cudaEnableDefault, &st);
        enc = (EncodeTiledFn)p;
    }
    encode_map(enc, &h_tmaps[0], xt,    (unsigned long long)Mrows, 256);  // A1
    encode_map(enc, &h_tmaps[1], wt,    (unsigned long long)QKVC,  64);   // B1 quarter
    encode_map(enc, &h_tmaps[2], oattn, (unsigned long long)Mrows, 256);  // A2
    encode_map(enc, &h_tmaps[3], wot,   (unsigned long long)Dd,    64);   // B2 quarter
    cudaMemcpyToSymbolAsync(g_tmaps, h_tmaps, sizeof(h_tmaps), 0,
                            cudaMemcpyHostToDevice, 0);

    cudaFuncSetAttribute(gemm_tf32, cudaFuncAttributeMaxDynamicSharedMemorySize, GEMM_SMEM);

    // 1) round x to tf32; transpose+round weights
    {
        size_t n4 = (size_t)Mrows * Dd / 4;
        round_kernel<<<(unsigned)((n4 + 255) / 256), 256>>>(x, xt, n4);
    }
    transpose_round<<<dim3(QKVC/32, Dd/32), 256>>>(Wqkv, wt, Dd, QKVC);
    transpose_round<<<dim3(Dd/32,  Dd/32), 256>>>(Wout, wot, Dd, Dd);

    // 2) qkv = x @ Wqkv  (tcgen05 tf32, 4-way B multicast, 6-stage pipeline)
    gemm_tf32<<<dim3(QKVC/NT, Mrows/MT), 256, GEMM_SMEM>>>(
        dmaps + 0, xt, wt, qkv, QKVC, nullptr);

    // 3) fused normalize + cross-covariance + temperature + softmax (split 8x)
    attn_part<<<dim3(Bc * Hh, NSPLIT), 256>>>();
    attn_final<<<dim3(Bc * Hh), 256>>>(temp);

    // 4) out = v @ attn  (writes tf32-rounded fp32)
    av_kernel<<<dim3(Bc * Hh, Nn / 64), 256>>>();

    // 5) final projection + bias (tcgen05 tf32)
    gemm_tf32<<<dim3(Dd/NT, Mrows/MT), 256, GEMM_SMEM>>>(
        dmaps + 2, oattn, wot, out, Dd, bout);
}

// round 14
// speedup vs baseline: 1.2001x; 1.2001x over previous
#include <cuda_runtime.h>
#include <cuda.h>
#include <cuda_bf16.h>
#include <math.h>
#include <stdint.h>

#define Bc 8
#define Nn 4096
#define Dd 768
#define Hh 12
#define dh 64
#define Mrows (Bc*Nn)      /* 32768 */
#define QKVC  (3*Dd)       /* 2304  */
#define GK    Dd           /* GEMM K = 768 */

// ---------------- scratch (device globals; allocation-free rule) -----------
__device__ float g_qkv[(size_t)Mrows * QKVC];          // 302 MB (v region used)
__device__ float g_attn[Bc*Hh*dh*dh];                  // 1.5 MB
__device__ __align__(256) float g_qkT[(size_t)Bc*Hh*128*Nn];  // 201 MB [bh][128][4096]
__device__ __align__(256) float g_xt[(size_t)Mrows*Dd];     // x rounded to tf32
__device__ __align__(256) float g_wt[(size_t)QKVC*Dd];      // Wqkv^T  [N,K] tf32
__device__ __align__(256) float g_wot[(size_t)Dd*Dd];       // Wout^T  [N,K] tf32
__device__ __align__(256) float g_oattn[(size_t)Mrows*Dd];  // v@attn  tf32
// tensormaps: [0]=x(A1), [1]=WqkvT(B1), [2]=oattn(A2), [3]=WoutT(B2), [4]=qkT
__device__ __align__(128) CUtensorMap g_tmaps[5];

// ---------------- arch feature gate -----------------------------------------
#if defined(__CUDA_ARCH_FEAT_SM103_ALL) || defined(__CUDA_ARCH_FEAT_SM100_ALL) || defined(__CUDA_ARCH_FEAT_SM101_ALL)
#define HAS_TCG 1
#else
#define HAS_TCG 0
#endif

// ---------------- common helpers --------------------------------------------
__device__ __forceinline__ uint32_t smem_u32(const void* p){
    uint32_t a;
    asm("{ .reg .u64 t; cvta.to.shared.u64 t, %1; cvt.u32.u64 %0, t; }" : "=r"(a) : "l"(p));
    return a;
}
__device__ __forceinline__ float rna_tf32(float v){
    uint32_t u;
    asm("cvt.rna.tf32.f32 %0, %1;" : "=r"(u) : "f"(v));
    return __uint_as_float(u);
}

// ---------------- GEMM tile geometry (R11 best config) -----------------------
#define MT 256
#define NT 256
#define KCH 32                  /* K elems per chunk: 32 fp32 = 128B rows */
#define NCH (GK/KCH)            /* 24 */
#define NSTAGE 3
#define OA 0                    /* A tile 256x32 fp32 = 32KB (halves +0/+16K) */
#define OB 32768                /* B tile 256x32 fp32 = 32KB (mc halves +16K) */
#define STAGE_BYTES 65536
#define SM_TILE0 1024
#define GEMM_SMEM (SM_TILE0 + NSTAGE*STAGE_BYTES) /* 197632 */

// attn_tc geometry
#define ACH 32                  /* n per chunk: 32 fp32 = 128B rows */
#define ANCH (Nn/ACH)           /* 128 */
#define ANST 6
#define ASTAGE_BYTES 16384      /* 128 rows x 128B */
#define ATTN_SMEM (SM_TILE0 + ANST*ASTAGE_BYTES)  /* 99328 */

#if HAS_TCG
// ---------------- tcgen05 / TMA helpers (arch-specific pass only) -----------
__device__ __forceinline__ uint32_t elect1(){
    uint32_t p;
    asm volatile("{\n\t.reg .pred p;\n\telect.sync _|p, 0xFFFFFFFF;\n\tselp.b32 %0, 1, 0, p;\n\t}" : "=r"(p));
    return p;
}
__device__ __forceinline__ uint32_t ctarank(){
    uint32_t r;
    asm("mov.u32 %0, %%cluster_ctarank;" : "=r"(r));
    return r;
}
// SW128 K-major descriptor: layout=2, version=1, SBO=64, LBO=1
static constexpr uint64_t DESC_BASE_SW128 =
    (uint64_t(2) << 61) | (uint64_t(1) << 46) | (uint64_t(64) << 32) | (uint64_t(1) << 16);
#define MK128(a) (DESC_BASE_SW128 | ((uint64_t)((a) >> 4) & 0x3FFF))
// idesc tf32, F32 accum: N=256 variant and N=128 variant
#define IDESC_N256 0x8400910u
#define IDESC_N128 0x8200910u

__device__ __forceinline__ void mma_tf32_ss(uint32_t d, uint64_t a, uint64_t b,
                                            uint32_t idesc, uint32_t en){
    asm volatile(
        "{\n\t.reg .pred p;\n\tsetp.ne.u32 p, %3, 0;\n\t"
        "tcgen05.mma.cta_group::1.kind::tf32 [%0], %1, %2, %4, {%5,%5,%5,%5}, p;\n\t}"
        :: "r"(d), "l"(a), "l"(b), "r"(en), "r"(idesc), "r"(0u) : "memory");
}
__device__ __forceinline__ void tc_commit(uint32_t mbar){
    asm volatile("tcgen05.commit.cta_group::1.mbarrier::arrive::one.shared::cluster.b64 [%0];"
                 :: "r"(mbar) : "memory");
}
__device__ __forceinline__ void tc_commit_mc(uint32_t mbar, uint16_t mask){
    asm volatile("tcgen05.commit.cta_group::1.mbarrier::arrive::one.shared::cluster.multicast::cluster.b64 [%0], %1;"
                 :: "r"(mbar), "h"(mask) : "memory");
}
__device__ __forceinline__ void mbar_init(uint32_t mbar, uint32_t cnt){
    asm volatile("mbarrier.init.shared.b64 [%0], %1;" :: "r"(mbar), "r"(cnt) : "memory");
}
__device__ __forceinline__ void mbar_wait(uint32_t mbar, uint32_t parity){
    asm volatile(
        "{\n\t.reg .pred P;\n\tWL_%=:\n\t"
        "mbarrier.try_wait.parity.acquire.cta.shared::cta.b64 P, [%0], %1, 0x989680;\n\t"
        "@P bra.uni WD_%=;\n\tbra.uni WL_%=;\n\tWD_%=:\n\t}"
        :: "r"(mbar), "r"(parity) : "memory");
}
__device__ __forceinline__ void mbar_wait_rlx(uint32_t mbar, uint32_t parity){
    asm volatile(
        "{\n\t.reg .pred P;\n\tWL_%=:\n\t"
        "mbarrier.try_wait.parity.relaxed.cta.shared::cta.b64 P, [%0], %1, 0x989680;\n\t"
        "@P bra.uni WD_%=;\n\tbra.uni WL_%=;\n\tWD_%=:\n\t}"
        :: "r"(mbar), "r"(parity) : "memory");
}
#define EXPECT_TX(mbar, bytes) \
    asm volatile("mbarrier.arrive.expect_tx.shared.b64 _, [%0], %1;" \
                 :: "r"(mbar), "r"((uint32_t)(bytes)) : "memory")
#define TMA2D(smem, map, x, y, mbar) \
    asm volatile("cp.async.bulk.tensor.2d.shared::cta.global.tile.mbarrier::complete_tx::bytes " \
                 "[%0], [%1, {%2, %3}], [%4];" \
                 :: "r"((uint32_t)(smem)), "l"(map), "r"((int)(x)), "r"((int)(y)), \
                    "r"((uint32_t)(mbar)) : "memory")
#define TMA2D_MC(smem, map, x, y, mbar, mask) \
    asm volatile("cp.async.bulk.tensor.2d.shared::cluster.global.tile.mbarrier::complete_tx::bytes.multicast::cluster " \
                 "[%0], [%1, {%2, %3}], [%4], %5;" \
                 :: "r"((uint32_t)(smem)), "l"(map), "r"((int)(x)), "r"((int)(y)), \
                    "r"((uint32_t)(mbar)), "h"((uint16_t)(mask)) : "memory")
#define CLUSTER_SYNC() do { \
    asm volatile("barrier.cluster.arrive.aligned;" ::: "memory"); \
    asm volatile("barrier.cluster.wait.aligned;" ::: "memory"); \
} while(0)

#define TC_FENCE_AFTER()  asm volatile("tcgen05.fence::after_thread_sync;" ::: "memory")
#define TC_FENCE_BEFORE() asm volatile("tcgen05.fence::before_thread_sync;" ::: "memory")
#define TC_WAIT_LD() asm volatile("tcgen05.wait::ld.sync.aligned;" ::: "memory")

#define LDTM32(r, addr) \
    asm volatile( \
        "tcgen05.ld.sync.aligned.32x32b.x32.b32 " \
        "{%0, %1, %2, %3, %4, %5, %6, %7, " \
        " %8, %9, %10, %11, %12, %13, %14, %15, " \
        " %16, %17, %18, %19, %20, %21, %22, %23, " \
        " %24, %25, %26, %27, %28, %29, %30, %31}, [%32];" \
        : "=r"((r)[0]),  "=r"((r)[1]),  "=r"((r)[2]),  "=r"((r)[3]), \
          "=r"((r)[4]),  "=r"((r)[5]),  "=r"((r)[6]),  "=r"((r)[7]), \
          "=r"((r)[8]),  "=r"((r)[9]),  "=r"((r)[10]), "=r"((r)[11]), \
          "=r"((r)[12]), "=r"((r)[13]), "=r"((r)[14]), "=r"((r)[15]), \
          "=r"((r)[16]), "=r"((r)[17]), "=r"((r)[18]), "=r"((r)[19]), \
          "=r"((r)[20]), "=r"((r)[21]), "=r"((r)[22]), "=r"((r)[23]), \
          "=r"((r)[24]), "=r"((r)[25]), "=r"((r)[26]), "=r"((r)[27]), \
          "=r"((r)[28]), "=r"((r)[29]), "=r"((r)[30]), "=r"((r)[31]) \
        : "r"(addr))
#endif  // HAS_TCG

// smem control offsets
#define MB_FULL(s)  (8  + (s)*8)
#define MB_EMPTY(s) (64 + (s)*8)
#define MB_DONE     120
#define SO_NORM     256              /* attn_tc: float norm[128] at +256 */

// ---------------------------------------------------------------------------
// Single-pass tf32 GEMM (R11 config):  C[M,Ntot] = A[M,GK] * B^T
// Cluster (1,2,1) B-multicast. Optional transposed q/k epilogue into Ct.
// ---------------------------------------------------------------------------
__global__ __launch_bounds__(256) __cluster_dims__(1, 2, 1)
void gemm_tf32(
    const CUtensorMap* __restrict__ tmaps,   // [A, B]
    const float* __restrict__ A, const float* __restrict__ B,
    float* __restrict__ C, int Ntot, const float* __restrict__ bias,
    float* __restrict__ Ct)                  // non-null: GEMM1 transposed q/k
{
    const int tid = threadIdx.x;
    const int row0 = blockIdx.y * MT;
    const int col0 = blockIdx.x * NT;

#if HAS_TCG
    extern __shared__ char smem[];
    const uint32_t sbase = smem_u32(smem);
    const int wid = tid >> 5;
    const int lane = tid & 31;
    const uint32_t rank = ctarank();

    if (wid == 0) {
        asm volatile("tcgen05.alloc.cta_group::1.sync.aligned.shared::cta.b32 [%0], %1;"
                     :: "r"(sbase), "r"(512u) : "memory");
    }
    if (tid == 0) {
        #pragma unroll
        for (int s = 0; s < NSTAGE; s++) {
            mbar_init(sbase + MB_FULL(s), 1);
            mbar_init(sbase + MB_EMPTY(s), 2);
        }
        mbar_init(sbase + MB_DONE, 1);
    }
    __syncthreads();
    uint32_t tmem;
    asm volatile("ld.shared.b32 %0, [%1];" : "=r"(tmem) : "r"(sbase));
    if (wid == 0)
        asm volatile("tcgen05.relinquish_alloc_permit.cta_group::1.sync.aligned;");

    CLUSTER_SYNC();

    uint32_t leader = 0, producer = 0;
    if (wid == 0) leader = elect1();
    if (wid == 1) producer = elect1();

    if (producer) {
        for (int ch = 0; ch < NCH; ch++) {
            const int st = ch % NSTAGE;
            const uint32_t sb = sbase + SM_TILE0 + st*STAGE_BYTES;
            if (ch >= NSTAGE)
                mbar_wait_rlx(sbase + MB_EMPTY(st), ((ch - NSTAGE) / NSTAGE) & 1);
            EXPECT_TX(sbase + MB_FULL(st), 65536u);
            TMA2D(sb + OA, tmaps + 0, ch*KCH, row0, sbase + MB_FULL(st));
            TMA2D_MC(sb + OB + rank*16384, tmaps + 1, ch*KCH,
                     col0 + (int)rank*128, sbase + MB_FULL(st), 3);
        }
    }

    if (leader) {
        uint32_t first = 0;
        const uint32_t tm0 = tmem, tm1 = tmem + 256;
        for (int ch = 0; ch < NCH; ch++) {
            const int st = ch % NSTAGE;
            mbar_wait(sbase + MB_FULL(st), (ch / NSTAGE) & 1);
            const uint32_t sb = sbase + SM_TILE0 + st*STAGE_BYTES;
            const uint64_t dA0 = MK128(sb + OA);
            const uint64_t dA1 = MK128(sb + OA + 16384);
            const uint64_t dB  = MK128(sb + OB);
            #pragma unroll
            for (int k = 0; k < 4; k++) {
                const uint64_t o = k*2;
                mma_tf32_ss(tm0, dA0 + o, dB + o, IDESC_N256, first);
                mma_tf32_ss(tm1, dA1 + o, dB + o, IDESC_N256, first);
                first = 1;
            }
            tc_commit_mc(sbase + MB_EMPTY(st), 3);
        }
        tc_commit(sbase + MB_DONE);
    }

    mbar_wait(sbase + MB_DONE, 0);
    TC_FENCE_AFTER();

    // ---- epilogue ----
    {
        const int mh = wid >> 2;
        const int r = row0 + mh*128 + (wid & 3)*32 + lane;
        const uint32_t tb = tmem + mh*256;
        const bool tr = (Ct != nullptr) && (col0 < 1536);
        const int bb = r >> 12, nn = r & 4095;
        float* crow = C + (size_t)r * Ntot;
        #pragma unroll
        for (int chk = 0; chk < 8; chk++) {
            uint32_t regs[32];
            LDTM32(regs, tb + chk*32);
            TC_WAIT_LD();
            const int c0 = col0 + chk*32;
            if (tr) {
                #pragma unroll
                for (int j = 0; j < 32; j++) {
                    const int c = c0 + j;
                    const int cc = (c < 768) ? c : c - 768;
                    const int qrow = (bb*Hh + (cc >> 6))*128
                                     + ((c < 768) ? 64 : 0) + (cc & 63);
                    Ct[(size_t)qrow * Nn + nn] = rna_tf32(__uint_as_float(regs[j]));
                }
            } else {
                #pragma unroll
                for (int j = 0; j < 32; j += 4) {
                    float4 v;
                    v.x = __uint_as_float(regs[j+0]);
                    v.y = __uint_as_float(regs[j+1]);
                    v.z = __uint_as_float(regs[j+2]);
                    v.w = __uint_as_float(regs[j+3]);
                    if (bias) {
                        v.x += bias[c0+j+0]; v.y += bias[c0+j+1];
                        v.z += bias[c0+j+2]; v.w += bias[c0+j+3];
                    }
                    *(float4*)(crow + c0 + j) = v;
                }
            }
        }
        TC_FENCE_BEFORE();
    }
    __syncthreads();
    CLUSTER_SYNC();
    if (tid == 0) {
        #pragma unroll
        for (int s = 0; s < NSTAGE; s++) {
            asm volatile("mbarrier.inval.shared.b64 [%0];" :: "r"(sbase + MB_FULL(s)) : "memory");
            asm volatile("mbarrier.inval.shared.b64 [%0];" :: "r"(sbase + MB_EMPTY(s)) : "memory");
        }
        asm volatile("mbarrier.inval.shared.b64 [%0];" :: "r"(sbase + MB_DONE) : "memory");
    }
    __syncthreads();
    if (wid == 0) {
        asm volatile("tcgen05.dealloc.cta_group::1.sync.aligned.b32 %0, %1;"
                     :: "r"(tmem), "r"(512u));
    }
    CLUSTER_SYNC();

#else
    (void)tmaps;
    for (int idx = tid; idx < MT*NT; idx += 256) {
        const int r = row0 + idx / NT;
        const int c = col0 + idx % NT;
        float s = bias ? bias[c] : 0.f;
        for (int k = 0; k < GK; k++)
            s = fmaf(A[(size_t)r * GK + k], B[(size_t)c * GK + k], s);
        if (Ct && c < 1536) {
            const int bb = r >> 12, nn = r & 4095;
            const int cc = (c < 768) ? c : c - 768;
            const int qrow = (bb*Hh + (cc >> 6))*128 + ((c < 768) ? 64 : 0) + (cc & 63);
            Ct[(size_t)qrow * Nn + nn] = s;
        } else {
            C[(size_t)r * Ntot + c] = s;
        }
    }
#endif
}

// ---------------------------------------------------------------------------
// attn_tc: per (b,h), D[128x128] = T T^T over n (T = [k;q], 128 x 4096),
// then norms from diag, temperature, softmax -> g_attn. grid 96, block 128.
// ---------------------------------------------------------------------------
__global__ __launch_bounds__(128) void attn_tc(
    const CUtensorMap* __restrict__ tmap, const float* __restrict__ temp)
{
    const int bh = blockIdx.x;
    const int tid = threadIdx.x;

#if HAS_TCG
    extern __shared__ char smem[];
    const uint32_t sbase = smem_u32(smem);
    const int wid = tid >> 5;
    const int lane = tid & 31;

    if (wid == 0) {
        asm volatile("tcgen05.alloc.cta_group::1.sync.aligned.shared::cta.b32 [%0], %1;"
                     :: "r"(sbase), "r"(128u) : "memory");
    }
    if (tid == 0) {
        #pragma unroll
        for (int s = 0; s < ANST; s++) {
            mbar_init(sbase + MB_FULL(s), 1);
            mbar_init(sbase + MB_EMPTY(s), 1);
        }
        mbar_init(sbase + MB_DONE, 1);
    }
    __syncthreads();
    uint32_t tmem;
    asm volatile("ld.shared.b32 %0, [%1];" : "=r"(tmem) : "r"(sbase));
    if (wid == 0)
        asm volatile("tcgen05.relinquish_alloc_permit.cta_group::1.sync.aligned;");
    __syncthreads();

    uint32_t leader = 0, producer = 0;
    if (wid == 0) leader = elect1();
    if (wid == 1) producer = elect1();

    if (producer) {
        for (int ch = 0; ch < ANCH; ch++) {
            const int st = ch % ANST;
            const uint32_t sb = sbase + SM_TILE0 + st*ASTAGE_BYTES;
            if (ch >= ANST)
                mbar_wait_rlx(sbase + MB_EMPTY(st), ((ch - ANST) / ANST) & 1);
            EXPECT_TX(sbase + MB_FULL(st), 16384u);
            TMA2D(sb, tmap, ch*ACH, bh*128, sbase + MB_FULL(st));
        }
    }

    if (leader) {
        uint32_t first = 0;
        for (int ch = 0; ch < ANCH; ch++) {
            const int st = ch % ANST;
            mbar_wait(sbase + MB_FULL(st), (ch / ANST) & 1);
            const uint64_t dT = MK128(sbase + SM_TILE0 + st*ASTAGE_BYTES);
            #pragma unroll
            for (int k = 0; k < 4; k++) {
                mma_tf32_ss(tmem, dT + k*2, dT + k*2, IDESC_N128, first);
                first = 1;
            }
            tc_commit(sbase + MB_EMPTY(st));
        }
        tc_commit(sbase + MB_DONE);
    }

    mbar_wait(sbase + MB_DONE, 0);
    TC_FENCE_AFTER();

    // ---- epilogue: D row r = wid*32+lane; cols 0..127 in regs ----
    {
        const int r = wid*32 + lane;
        uint32_t regs[128];
        #pragma unroll
        for (int chk = 0; chk < 4; chk++) {
            LDTM32(regs + chk*32, tmem + chk*32);
        }
        TC_WAIT_LD();
        TC_FENCE_BEFORE();

        float* normp = (float*)(smem + SO_NORM);
        normp[r] = fmaxf(sqrtf(__uint_as_float(regs[r])), 1e-12f);
        __syncthreads();

        if (r < 64) {   // attn row p = r: raw[p][q] = D[r][64+q]
            const float tv = temp[bh % Hh];
            const float nk = normp[r];
            float vals[64];
            float m = -1e30f;
            #pragma unroll
            for (int q = 0; q < 64; q++) {
                vals[q] = __uint_as_float(regs[64+q]) * tv / (nk * normp[64+q]);
                m = fmaxf(m, vals[q]);
            }
            float s = 0.f;
            #pragma unroll
            for (int q = 0; q < 64; q++) { vals[q] = expf(vals[q] - m); s += vals[q]; }
            const float inv = 1.f / s;
            float* op = g_attn + (size_t)bh * 4096 + r * 64;
            #pragma unroll
            for (int q = 0; q < 64; q += 4) {
                float4 v;
                v.x = vals[q+0]*inv; v.y = vals[q+1]*inv;
                v.z = vals[q+2]*inv; v.w = vals[q+3]*inv;
                *(float4*)(op + q) = v;
            }
        }
    }
    __syncthreads();
    if (tid == 0) {
        #pragma unroll
        for (int s = 0; s < ANST; s++) {
            asm volatile("mbarrier.inval.shared.b64 [%0];" :: "r"(sbase + MB_FULL(s)) : "memory");
            asm volatile("mbarrier.inval.shared.b64 [%0];" :: "r"(sbase + MB_EMPTY(s)) : "memory");
        }
        asm volatile("mbarrier.inval.shared.b64 [%0];" :: "r"(sbase + MB_DONE) : "memory");
    }
    __syncthreads();
    if (wid == 0) {
        asm volatile("tcgen05.dealloc.cta_group::1.sync.aligned.b32 %0, %1;"
                     :: "r"(tmem), "r"(128u));
    }

#else
    // ---- correctness-only fallback ----
    (void)tmap;
    __shared__ float Ds[128];   // placeholder; do serial math
    (void)Ds;
    if (tid == 0) {
        const float tv = temp[bh % Hh];
        const float* T = g_qkT + (size_t)bh * 128 * Nn;
        float normv[128];
        for (int i = 0; i < 128; i++) {
            double s = 0;
            for (int n = 0; n < Nn; n++) { float v = T[(size_t)i*Nn+n]; s += (double)v*v; }
            normv[i] = fmaxf(sqrtf((float)s), 1e-12f);
        }
        for (int p = 0; p < 64; p++) {
            float vals[64]; float m = -1e30f;
            for (int q = 0; q < 64; q++) {
                double s = 0;
                for (int n = 0; n < Nn; n++)
                    s += (double)T[(size_t)p*Nn+n] * T[(size_t)(64+q)*Nn+n];
                vals[q] = (float)s * tv / (normv[p] * normv[64+q]);
                m = fmaxf(m, vals[q]);
            }
            float s = 0;
            for (int q = 0; q < 64; q++) { vals[q] = expf(vals[q]-m); s += vals[q]; }
            for (int q = 0; q < 64; q++)
                g_attn[(size_t)bh*4096 + p*64 + q] = vals[q] / s;
        }
    }
#endif
}

// ---------------------------------------------------------------------------
// fp32 -> tf32-rounded fp32 (elementwise)
// ---------------------------------------------------------------------------
__global__ __launch_bounds__(256) void round_kernel(
    const float* __restrict__ in, float* __restrict__ outp, size_t n4)
{
    const size_t i = (size_t)blockIdx.x * blockDim.x + threadIdx.x;
    if (i >= n4) return;
    float4 v = ((const float4*)in)[i];
    v.x = rna_tf32(v.x); v.y = rna_tf32(v.y);
    v.z = rna_tf32(v.z); v.w = rna_tf32(v.w);
    ((float4*)outp)[i] = v;
}

// ---------------------------------------------------------------------------
// W [K,N] fp32 -> transposed tf32-rounded [N,K] row-major
// ---------------------------------------------------------------------------
__global__ __launch_bounds__(256) void transpose_round(
    const float* __restrict__ W, float* __restrict__ o, int K, int N)
{
    __shared__ float t[32][33];
    const int n0 = blockIdx.x * 32, k0 = blockIdx.y * 32;
    const int tx = threadIdx.x & 31, ty = threadIdx.x >> 5;
    #pragma unroll
    for (int i = ty; i < 32; i += 8)
        t[i][tx] = W[(size_t)(k0 + i) * N + n0 + tx];
    __syncthreads();
    #pragma unroll
    for (int i = ty; i < 32; i += 8)
        o[(size_t)(n0 + i) * K + k0 + tx] = rna_tf32(t[tx][i]);
}

// ---------------------------------------------------------------------------
// out[b,h,n,q] = sum_p v[n,p] attn[p,q]  -> tf32-rounded fp32, row-major
// ---------------------------------------------------------------------------
__global__ __launch_bounds__(256) void av_kernel()
{
    const int bh = blockIdx.x;
    const int nt = blockIdx.y;
    const int b  = bh / Hh, h = bh % Hh;
    const int tid = threadIdx.x;
    const int tx = tid & 15, ty = tid >> 4;

    __shared__ float At[64][68];
    __shared__ float Vs[64][68];

    {
        const float* ap = g_attn + (size_t)bh * 4096;
        #pragma unroll
        for (int pp = 0; pp < 4; pp++) {
            const int idx = pp * 1024 + tid * 4;
            *(float4*)&At[idx >> 6][idx & 63] = *(const float4*)(ap + idx);
        }
    }
    const int lr = tid >> 4, lc = (tid & 15) << 2;
    const int voff = 2 * Dd + h * dh;
    const size_t rowbase = (size_t)b * Nn + nt * 64;
    #pragma unroll
    for (int pp = 0; pp < 64; pp += 16)
        *(float4*)&Vs[pp + lr][lc] =
            *(const float4*)(g_qkv + (rowbase + pp + lr) * QKVC + voff + lc);
    __syncthreads();

    float acc[4][4];
    #pragma unroll
    for (int i = 0; i < 4; i++)
        #pragma unroll
        for (int j = 0; j < 4; j++) acc[i][j] = 0.f;

    #pragma unroll 8
    for (int p = 0; p < 64; p++) {
        float ra[4];
        *(float4*)ra = *(const float4*)&At[p][tx * 4];
        float rv[4];
        #pragma unroll
        for (int i = 0; i < 4; i++) rv[i] = Vs[ty * 4 + i][p];
        #pragma unroll
        for (int i = 0; i < 4; i++)
            #pragma unroll
            for (int j = 0; j < 4; j++)
                acc[i][j] = fmaf(rv[i], ra[j], acc[i][j]);
    }

    #pragma unroll
    for (int i = 0; i < 4; i++) {
        const size_t r = rowbase + ty * 4 + i;
        float4 v;
        v.x = rna_tf32(acc[i][0]); v.y = rna_tf32(acc[i][1]);
        v.z = rna_tf32(acc[i][2]); v.w = rna_tf32(acc[i][3]);
        *(float4*)(g_oattn + r * Dd + h * dh + tx * 4) = v;
    }
}

// ---------------------------------------------------------------------------
// host: tensormap construction via driver entry point (no -lcuda needed)
// ---------------------------------------------------------------------------
typedef CUresult (*EncodeTiledFn)(
    CUtensorMap*, CUtensorMapDataType, cuuint32_t, void*,
    const cuuint64_t*, const cuuint64_t*, const cuuint32_t*, const cuuint32_t*,
    CUtensorMapInterleave, CUtensorMapSwizzle, CUtensorMapL2promotion,
    CUtensorMapFloatOOBfill);

static void encode_map(EncodeTiledFn enc, CUtensorMap* m, void* base,
                       unsigned long long cols, unsigned long long nrows,
                       unsigned boxrows)
{
    cuuint64_t dims[2]    = {cols, nrows};
    cuuint64_t strides[1] = {cols * 4};
    cuuint32_t box[2]     = {32u, boxrows};            // 128B x boxrows
    cuuint32_t estr[2]    = {1u, 1u};
    enc(m, CU_TENSOR_MAP_DATA_TYPE_FLOAT32, 2, base, dims, strides, box, estr,
        CU_TENSOR_MAP_INTERLEAVE_NONE, CU_TENSOR_MAP_SWIZZLE_128B,
        CU_TENSOR_MAP_L2_PROMOTION_L2_128B, CU_TENSOR_MAP_FLOAT_OOB_FILL_NONE);
}

extern "C" void kernel_launch(void* const* d_in, const int* in_sizes, int n_in,
                              void* d_out, int out_size)
{
    const float* x     = (const float*)d_in[0];
    const float* Wqkv  = (const float*)d_in[1];
    const float* temp  = (const float*)d_in[2];
    const float* Wout  = (const float*)d_in[3];
    const float* bout  = (const float*)d_in[4];
    float* out = (float*)d_out;

    float *qkv, *xt, *wt, *wot, *oattn, *qkT;
    cudaGetSymbolAddress((void**)&qkv,   g_qkv);
    cudaGetSymbolAddress((void**)&xt,    g_xt);
    cudaGetSymbolAddress((void**)&wt,    g_wt);
    cudaGetSymbolAddress((void**)&wot,   g_wot);
    cudaGetSymbolAddress((void**)&oattn, g_oattn);
    cudaGetSymbolAddress((void**)&qkT,   g_qkT);
    CUtensorMap* dmaps;
    cudaGetSymbolAddress((void**)&dmaps, g_tmaps);

    static CUtensorMap h_tmaps[5];
    static EncodeTiledFn enc = nullptr;
    if (!enc) {
        void* p = nullptr;
        cudaDriverEntryPointQueryResult st;
        cudaGetDriverEntryPoint("cuTensorMapEncodeTiled", &p, cudaEnableDefault, &st);
        enc = (EncodeTiledFn)p;
    }
    encode_map(enc, &h_tmaps[0], xt,    GK, (unsigned long long)Mrows, 256);
    encode_map(enc, &h_tmaps[1], wt,    GK, (unsigned long long)QKVC, 128);
    encode_map(enc, &h_tmaps[2], oattn, GK, (unsigned long long)Mrows, 256);
    encode_map(enc, &h_tmaps[3], wot,   GK, (unsigned long long)Dd,   128);
    encode_map(enc, &h_tmaps[4], qkT,   Nn, (unsigned long long)(Bc*Hh*128), 128);
    cudaMemcpyToSymbolAsync(g_tmaps, h_tmaps, sizeof(h_tmaps), 0,
                            cudaMemcpyHostToDevice, 0);

    cudaFuncSetAttribute(gemm_tf32, cudaFuncAttributeMaxDynamicSharedMemorySize, GEMM_SMEM);
    cudaFuncSetAttribute(attn_tc,   cudaFuncAttributeMaxDynamicSharedMemorySize, ATTN_SMEM);

    // 1) round x to tf32; transpose+round weights
    {
        size_t n4 = (size_t)Mrows * Dd / 4;
        round_kernel<<<(unsigned)((n4 + 255) / 256), 256>>>(x, xt, n4);
    }
    transpose_round<<<dim3(QKVC/32, Dd/32), 256>>>(Wqkv, wt, Dd, QKVC);
    transpose_round<<<dim3(Dd/32,  Dd/32), 256>>>(Wout, wot, Dd, Dd);

    // 2) qkv = x @ Wqkv; q,k written transposed into g_qkT, v into g_qkv
    gemm_tf32<<<dim3(QKVC/NT, Mrows/MT), 256, GEMM_SMEM>>>(
        dmaps + 0, xt, wt, qkv, QKVC, nullptr, qkT);

    // 3) attention via tcgen05: D = [k;q][k;q]^T -> norms + softmax
    attn_tc<<<dim3(Bc * Hh), 128, ATTN_SMEM>>>(dmaps + 4, temp);

    // 4) out = v @ attn
    av_kernel<<<dim3(Bc * Hh, Nn / 64), 256>>>();

    // 5) final projection + bias
    gemm_tf32<<<dim3(Dd/NT, Mrows/MT), 256, GEMM_SMEM>>>(
        dmaps + 2, oattn, wot, out, Dd, bout, nullptr);
}

// round 15
// speedup vs baseline: 1.3732x; 1.1442x over previous
#include <cuda_runtime.h>
#include <cuda.h>
#include <cuda_fp16.h>
#include <math.h>
#include <stdint.h>

#define Bc 8
#define Nn 4096
#define Dd 768
#define Hh 12
#define dh 64
#define Mrows (Bc*Nn)      /* 32768 */
#define QKVC  (3*Dd)       /* 2304  */
#define GK    Dd           /* GEMM K = 768 */

// ---------------- scratch (device globals; allocation-free rule) -----------
__device__ float g_attn[Bc*Hh*dh*dh];                        // 1.5 MB
__device__ __align__(256) __half g_qkT[(size_t)Bc*Hh*128*Nn];  // 100 MB [bh][128][4096]
__device__ __align__(256) __half g_vh[(size_t)Mrows*Dd];       // 50 MB  v fp16
__device__ __align__(256) __half g_xh[(size_t)Mrows*Dd];       // x fp16
__device__ __align__(256) __half g_wth[(size_t)QKVC*Dd];       // Wqkv^T [N,K] fp16
__device__ __align__(256) __half g_woth[(size_t)Dd*Dd];        // Wout^T [N,K] fp16
__device__ __align__(256) __half g_oatth[(size_t)Mrows*Dd];    // v@attn fp16
// tensormaps: [0]=xh(A1), [1]=wth(B1), [2]=oatth(A2), [3]=woth(B2), [4]=qkT
__device__ __align__(128) CUtensorMap g_tmaps[5];

// ---------------- arch feature gate -----------------------------------------
#if defined(__CUDA_ARCH_FEAT_SM103_ALL) || defined(__CUDA_ARCH_FEAT_SM100_ALL) || defined(__CUDA_ARCH_FEAT_SM101_ALL)
#define HAS_TCG 1
#else
#define HAS_TCG 0
#endif

// ---------------- common helpers --------------------------------------------
__device__ __forceinline__ uint32_t smem_u32(const void* p){
    uint32_t a;
    asm("{ .reg .u64 t; cvta.to.shared.u64 t, %1; cvt.u32.u64 %0, t; }" : "=r"(a) : "l"(p));
    return a;
}

// ---------------- GEMM tile geometry (fp16) ----------------------------------
#define MT 256
#define NT 256
#define KCH 64                  /* K elems per chunk: 64 fp16 = 128B rows */
#define NCH (GK/KCH)            /* 12 */
#define NSTAGE 3
#define OA 0                    /* A tile 256x64 fp16 = 32KB (M halves +16K) */
#define OB 32768                /* B tile 256x64 fp16 = 32KB (mc halves +16K) */
#define STAGE_BYTES 65536
#define SM_TILE0 1024
#define GEMM_SMEM (SM_TILE0 + NSTAGE*STAGE_BYTES) /* 197632 */

// attn_tc geometry (fp16)
#define ACH 64                  /* n per chunk: 64 fp16 = 128B rows */
#define ANCH (Nn/ACH)           /* 64 */
#define ANST 6
#define ASTAGE_BYTES 16384      /* 128 rows x 128B */
#define ATTN_SMEM (SM_TILE0 + ANST*ASTAGE_BYTES)  /* 99328 */

#if HAS_TCG
// ---------------- tcgen05 / TMA helpers (arch-specific pass only) -----------
__device__ __forceinline__ uint32_t elect1(){
    uint32_t p;
    asm volatile("{\n\t.reg .pred p;\n\telect.sync _|p, 0xFFFFFFFF;\n\tselp.b32 %0, 1, 0, p;\n\t}" : "=r"(p));
    return p;
}
__device__ __forceinline__ uint32_t ctarank(){
    uint32_t r;
    asm("mov.u32 %0, %%cluster_ctarank;" : "=r"(r));
    return r;
}
// SW128 K-major descriptor: layout=2, version=1, SBO=64, LBO=1 (128B rows)
static constexpr uint64_t DESC_BASE_SW128 =
    (uint64_t(2) << 61) | (uint64_t(1) << 46) | (uint64_t(64) << 32) | (uint64_t(1) << 16);
#define MK128(a) (DESC_BASE_SW128 | ((uint64_t)((a) >> 4) & 0x3FFF))
// idesc fp16 (atype=btype=0), F32 accum (1<<4), M=128 (8<<24)
#define IDESC_N256 0x8400010u
#define IDESC_N128 0x8200010u

__device__ __forceinline__ void mma_f16_ss(uint32_t d, uint64_t a, uint64_t b,
                                           uint32_t idesc, uint32_t en){
    asm volatile(
        "{\n\t.reg .pred p;\n\tsetp.ne.u32 p, %3, 0;\n\t"
        "tcgen05.mma.cta_group::1.kind::f16 [%0], %1, %2, %4, {%5,%5,%5,%5}, p;\n\t}"
        :: "r"(d), "l"(a), "l"(b), "r"(en), "r"(idesc), "r"(0u) : "memory");
}
__device__ __forceinline__ void tc_commit(uint32_t mbar){
    asm volatile("tcgen05.commit.cta_group::1.mbarrier::arrive::one.shared::cluster.b64 [%0];"
                 :: "r"(mbar) : "memory");
}
__device__ __forceinline__ void tc_commit_mc(uint32_t mbar, uint16_t mask){
    asm volatile("tcgen05.commit.cta_group::1.mbarrier::arrive::one.shared::cluster.multicast::cluster.b64 [%0], %1;"
                 :: "r"(mbar), "h"(mask) : "memory");
}
__device__ __forceinline__ void mbar_init(uint32_t mbar, uint32_t cnt){
    asm volatile("mbarrier.init.shared.b64 [%0], %1;" :: "r"(mbar), "r"(cnt) : "memory");
}
__device__ __forceinline__ void mbar_wait(uint32_t mbar, uint32_t parity){
    asm volatile(
        "{\n\t.reg .pred P;\n\tWL_%=:\n\t"
        "mbarrier.try_wait.parity.acquire.cta.shared::cta.b64 P, [%0], %1, 0x989680;\n\t"
        "@P bra.uni WD_%=;\n\tbra.uni WL_%=;\n\tWD_%=:\n\t}"
        :: "r"(mbar), "r"(parity) : "memory");
}
__device__ __forceinline__ void mbar_wait_rlx(uint32_t mbar, uint32_t parity){
    asm volatile(
        "{\n\t.reg .pred P;\n\tWL_%=:\n\t"
        "mbarrier.try_wait.parity.relaxed.cta.shared::cta.b64 P, [%0], %1, 0x989680;\n\t"
        "@P bra.uni WD_%=;\n\tbra.uni WL_%=;\n\tWD_%=:\n\t}"
        :: "r"(mbar), "r"(parity) : "memory");
}
#define EXPECT_TX(mbar, bytes) \
    asm volatile("mbarrier.arrive.expect_tx.shared.b64 _, [%0], %1;" \
                 :: "r"(mbar), "r"((uint32_t)(bytes)) : "memory")
#define TMA2D(smem, map, x, y, mbar) \
    asm volatile("cp.async.bulk.tensor.2d.shared::cta.global.tile.mbarrier::complete_tx::bytes " \
                 "[%0], [%1, {%2, %3}], [%4];" \
                 :: "r"((uint32_t)(smem)), "l"(map), "r"((int)(x)), "r"((int)(y)), \
                    "r"((uint32_t)(mbar)) : "memory")
#define TMA2D_MC(smem, map, x, y, mbar, mask) \
    asm volatile("cp.async.bulk.tensor.2d.shared::cluster.global.tile.mbarrier::complete_tx::bytes.multicast::cluster " \
                 "[%0], [%1, {%2, %3}], [%4], %5;" \
                 :: "r"((uint32_t)(smem)), "l"(map), "r"((int)(x)), "r"((int)(y)), \
                    "r"((uint32_t)(mbar)), "h"((uint16_t)(mask)) : "memory")
#define CLUSTER_SYNC() do { \
    asm volatile("barrier.cluster.arrive.aligned;" ::: "memory"); \
    asm volatile("barrier.cluster.wait.aligned;" ::: "memory"); \
} while(0)

#define TC_FENCE_AFTER()  asm volatile("tcgen05.fence::after_thread_sync;" ::: "memory")
#define TC_FENCE_BEFORE() asm volatile("tcgen05.fence::before_thread_sync;" ::: "memory")
#define TC_WAIT_LD() asm volatile("tcgen05.wait::ld.sync.aligned;" ::: "memory")

#define LDTM32(r, addr) \
    asm volatile( \
        "tcgen05.ld.sync.aligned.32x32b.x32.b32 " \
        "{%0, %1, %2, %3, %4, %5, %6, %7, " \
        " %8, %9, %10, %11, %12, %13, %14, %15, " \
        " %16, %17, %18, %19, %20, %21, %22, %23, " \
        " %24, %25, %26, %27, %28, %29, %30, %31}, [%32];" \
        : "=r"((r)[0]),  "=r"((r)[1]),  "=r"((r)[2]),  "=r"((r)[3]), \
          "=r"((r)[4]),  "=r"((r)[5]),  "=r"((r)[6]),  "=r"((r)[7]), \
          "=r"((r)[8]),  "=r"((r)[9]),  "=r"((r)[10]), "=r"((r)[11]), \
          "=r"((r)[12]), "=r"((r)[13]), "=r"((r)[14]), "=r"((r)[15]), \
          "=r"((r)[16]), "=r"((r)[17]), "=r"((r)[18]), "=r"((r)[19]), \
          "=r"((r)[20]), "=r"((r)[21]), "=r"((r)[22]), "=r"((r)[23]), \
          "=r"((r)[24]), "=r"((r)[25]), "=r"((r)[26]), "=r"((r)[27]), \
          "=r"((r)[28]), "=r"((r)[29]), "=r"((r)[30]), "=r"((r)[31]) \
        : "r"(addr))
#endif  // HAS_TCG

// smem control offsets
#define MB_FULL(s)  (8  + (s)*8)
#define MB_EMPTY(s) (64 + (s)*8)
#define MB_DONE     120
#define SO_NORM     256              /* attn_tc: float norm[128] at +256 */

// ---------------------------------------------------------------------------
// fp16 tcgen05 GEMM:  C = A[M,GK] * B^T  (A,B fp16 K-major row-major)
// GEMM1 mode (qkT/vh non-null): writes q,k transposed fp16 + v fp16.
// GEMM2 mode: writes fp32 C + bias.
// ---------------------------------------------------------------------------
__global__ __launch_bounds__(256) __cluster_dims__(1, 2, 1)
void gemm_f16(
    const CUtensorMap* __restrict__ tmaps,   // [A, B]
    const __half* __restrict__ A, const __half* __restrict__ B,
    float* __restrict__ C, int Ntot, const float* __restrict__ bias,
    __half* __restrict__ qkT, __half* __restrict__ vh)
{
    const int tid = threadIdx.x;
    const int row0 = blockIdx.y * MT;
    const int col0 = blockIdx.x * NT;

#if HAS_TCG
    extern __shared__ char smem[];
    const uint32_t sbase = smem_u32(smem);
    const int wid = tid >> 5;
    const int lane = tid & 31;
    const uint32_t rank = ctarank();

    if (wid == 0) {
        asm volatile("tcgen05.alloc.cta_group::1.sync.aligned.shared::cta.b32 [%0], %1;"
                     :: "r"(sbase), "r"(512u) : "memory");
    }
    if (tid == 0) {
        #pragma unroll
        for (int s = 0; s < NSTAGE; s++) {
            mbar_init(sbase + MB_FULL(s), 1);
            mbar_init(sbase + MB_EMPTY(s), 2);
        }
        mbar_init(sbase + MB_DONE, 1);
    }
    __syncthreads();
    uint32_t tmem;
    asm volatile("ld.shared.b32 %0, [%1];" : "=r"(tmem) : "r"(sbase));
    if (wid == 0)
        asm volatile("tcgen05.relinquish_alloc_permit.cta_group::1.sync.aligned;");

    CLUSTER_SYNC();

    uint32_t leader = 0, producer = 0;
    if (wid == 0) leader = elect1();
    if (wid == 1) producer = elect1();

    if (producer) {
        for (int ch = 0; ch < NCH; ch++) {
            const int st = ch % NSTAGE;
            const uint32_t sb = sbase + SM_TILE0 + st*STAGE_BYTES;
            if (ch >= NSTAGE)
                mbar_wait_rlx(sbase + MB_EMPTY(st), ((ch - NSTAGE) / NSTAGE) & 1);
            EXPECT_TX(sbase + MB_FULL(st), 65536u);
            TMA2D(sb + OA, tmaps + 0, ch*KCH, row0, sbase + MB_FULL(st));
            TMA2D_MC(sb + OB + rank*16384, tmaps + 1, ch*KCH,
                     col0 + (int)rank*128, sbase + MB_FULL(st), 3);
        }
    }

    if (leader) {
        uint32_t first = 0;
        const uint32_t tm0 = tmem, tm1 = tmem + 256;
        for (int ch = 0; ch < NCH; ch++) {
            const int st = ch % NSTAGE;
            mbar_wait(sbase + MB_FULL(st), (ch / NSTAGE) & 1);
            const uint32_t sb = sbase + SM_TILE0 + st*STAGE_BYTES;
            const uint64_t dA0 = MK128(sb + OA);
            const uint64_t dA1 = MK128(sb + OA + 16384);
            const uint64_t dB  = MK128(sb + OB);
            #pragma unroll
            for (int k = 0; k < 4; k++) {      // K=16 per f16 MMA; 4 k-steps
                const uint64_t o = k*2;        // 32B per k-step
                mma_f16_ss(tm0, dA0 + o, dB + o, IDESC_N256, first);
                mma_f16_ss(tm1, dA1 + o, dB + o, IDESC_N256, first);
                first = 1;
            }
            tc_commit_mc(sbase + MB_EMPTY(st), 3);
        }
        tc_commit(sbase + MB_DONE);
    }

    mbar_wait(sbase + MB_DONE, 0);
    TC_FENCE_AFTER();

    // ---- epilogue ----
    {
        const int mh = wid >> 2;
        const int r = row0 + mh*128 + (wid & 3)*32 + lane;
        const uint32_t tb = tmem + mh*256;
        const bool g1 = (qkT != nullptr);
        const int bb = r >> 12, nn = r & 4095;
        float* crow = C ? (C + (size_t)r * Ntot) : nullptr;
        #pragma unroll
        for (int chk = 0; chk < 8; chk++) {
            uint32_t regs[32];
            LDTM32(regs, tb + chk*32);
            TC_WAIT_LD();
            const int c0 = col0 + chk*32;
            if (g1) {
                if (c0 < 1536) {   // q (0..767) / k (768..1535) -> transposed fp16
                    #pragma unroll
                    for (int j = 0; j < 32; j++) {
                        const int c = c0 + j;
                        const int cc = (c < 768) ? c : c - 768;
                        const int qrow = (bb*Hh + (cc >> 6))*128
                                         + ((c < 768) ? 64 : 0) + (cc & 63);
                        qkT[(size_t)qrow * Nn + nn] =
                            __float2half_rn(__uint_as_float(regs[j]));
                    }
                } else {           // v -> fp16 row-major [Mrows x 768]
                    __half* vrow = vh + (size_t)r * Dd + (c0 - 1536);
                    #pragma unroll
                    for (int j = 0; j < 32; j += 2) {
                        __half2 hv = __floats2half2_rn(
                            __uint_as_float(regs[j]), __uint_as_float(regs[j+1]));
                        *(__half2*)(vrow + j) = hv;
                    }
                }
            } else {
                #pragma unroll
                for (int j = 0; j < 32; j += 4) {
                    float4 v;
                    v.x = __uint_as_float(regs[j+0]);
                    v.y = __uint_as_float(regs[j+1]);
                    v.z = __uint_as_float(regs[j+2]);
                    v.w = __uint_as_float(regs[j+3]);
                    if (bias) {
                        v.x += bias[c0+j+0]; v.y += bias[c0+j+1];
                        v.z += bias[c0+j+2]; v.w += bias[c0+j+3];
                    }
                    *(float4*)(crow + c0 + j) = v;
                }
            }
        }
        TC_FENCE_BEFORE();
    }
    __syncthreads();
    CLUSTER_SYNC();
    if (tid == 0) {
        #pragma unroll
        for (int s = 0; s < NSTAGE; s++) {
            asm volatile("mbarrier.inval.shared.b64 [%0];" :: "r"(sbase + MB_FULL(s)) : "memory");
            asm volatile("mbarrier.inval.shared.b64 [%0];" :: "r"(sbase + MB_EMPTY(s)) : "memory");
        }
        asm volatile("mbarrier.inval.shared.b64 [%0];" :: "r"(sbase + MB_DONE) : "memory");
    }
    __syncthreads();
    if (wid == 0) {
        asm volatile("tcgen05.dealloc.cta_group::1.sync.aligned.b32 %0, %1;"
                     :: "r"(tmem), "r"(512u));
    }
    CLUSTER_SYNC();

#else
    (void)tmaps;
    for (int idx = tid; idx < MT*NT; idx += 256) {
        const int r = row0 + idx / NT;
        const int c = col0 + idx % NT;
        float s = bias ? bias[c] : 0.f;
        for (int k = 0; k < GK; k++)
            s = fmaf(__half2float(A[(size_t)r * GK + k]),
                     __half2float(B[(size_t)c * GK + k]), s);
        if (qkT) {
            if (c < 1536) {
                const int bb = r >> 12, nn = r & 4095;
                const int cc = (c < 768) ? c : c - 768;
                const int qrow = (bb*Hh + (cc >> 6))*128 + ((c < 768) ? 64 : 0) + (cc & 63);
                qkT[(size_t)qrow * Nn + nn] = __float2half_rn(s);
            } else {
                vh[(size_t)r * Dd + (c - 1536)] = __float2half_rn(s);
            }
        } else {
            C[(size_t)r * Ntot + c] = s;
        }
    }
#endif
}

// ---------------------------------------------------------------------------
// attn_tc: per (b,h), D[128x128] = T T^T over n (T = [k;q] fp16, 128 x 4096),
// then norms from diag, temperature, softmax -> g_attn. grid 96, block 128.
// ---------------------------------------------------------------------------
__global__ __launch_bounds__(128) void attn_tc(
    const CUtensorMap* __restrict__ tmap, const float* __restrict__ temp)
{
    const int bh = blockIdx.x;
    const int tid = threadIdx.x;

#if HAS_TCG
    extern __shared__ char smem[];
    const uint32_t sbase = smem_u32(smem);
    const int wid = tid >> 5;
    const int lane = tid & 31;

    if (wid == 0) {
        asm volatile("tcgen05.alloc.cta_group::1.sync.aligned.shared::cta.b32 [%0], %1;"
                     :: "r"(sbase), "r"(128u) : "memory");
    }
    if (tid == 0) {
        #pragma unroll
        for (int s = 0; s < ANST; s++) {
            mbar_init(sbase + MB_FULL(s), 1);
            mbar_init(sbase + MB_EMPTY(s), 1);
        }
        mbar_init(sbase + MB_DONE, 1);
    }
    __syncthreads();
    uint32_t tmem;
    asm volatile("ld.shared.b32 %0, [%1];" : "=r"(tmem) : "r"(sbase));
    if (wid == 0)
        asm volatile("tcgen05.relinquish_alloc_permit.cta_group::1.sync.aligned;");
    __syncthreads();

    uint32_t leader = 0, producer = 0;
    if (wid == 0) leader = elect1();
    if (wid == 1) producer = elect1();

    if (producer) {
        for (int ch = 0; ch < ANCH; ch++) {
            const int st = ch % ANST;
            const uint32_t sb = sbase + SM_TILE0 + st*ASTAGE_BYTES;
            if (ch >= ANST)
                mbar_wait_rlx(sbase + MB_EMPTY(st), ((ch - ANST) / ANST) & 1);
            EXPECT_TX(sbase + MB_FULL(st), 16384u);
            TMA2D(sb, tmap, ch*ACH, bh*128, sbase + MB_FULL(st));
        }
    }

    if (leader) {
        uint32_t first = 0;
        for (int ch = 0; ch < ANCH; ch++) {
            const int st = ch % ANST;
            mbar_wait(sbase + MB_FULL(st), (ch / ANST) & 1);
            const uint64_t dT = MK128(sbase + SM_TILE0 + st*ASTAGE_BYTES);
            #pragma unroll
            for (int k = 0; k < 4; k++) {
                mma_f16_ss(tmem, dT + k*2, dT + k*2, IDESC_N128, first);
                first = 1;
            }
            tc_commit(sbase + MB_EMPTY(st));
        }
        tc_commit(sbase + MB_DONE);
    }

    mbar_wait(sbase + MB_DONE, 0);
    TC_FENCE_AFTER();

    {
        const int r = wid*32 + lane;
        uint32_t regs[128];
        #pragma unroll
        for (int chk = 0; chk < 4; chk++) {
            LDTM32(regs + chk*32, tmem + chk*32);
        }
        TC_WAIT_LD();
        TC_FENCE_BEFORE();

        float* normp = (float*)(smem + SO_NORM);
        normp[r] = fmaxf(sqrtf(__uint_as_float(regs[r])), 1e-12f);
        __syncthreads();

        if (r < 64) {
            const float tv = temp[bh % Hh];
            const float nk = normp[r];
            float vals[64];
            float m = -1e30f;
            #pragma unroll
            for (int q = 0; q < 64; q++) {
                vals[q] = __uint_as_float(regs[64+q]) * tv / (nk * normp[64+q]);
                m = fmaxf(m, vals[q]);
            }
            float s = 0.f;
            #pragma unroll
            for (int q = 0; q < 64; q++) { vals[q] = expf(vals[q] - m); s += vals[q]; }
            const float inv = 1.f / s;
            float* op = g_attn + (size_t)bh * 4096 + r * 64;
            #pragma unroll
            for (int q = 0; q < 64; q += 4) {
                float4 v;
                v.x = vals[q+0]*inv; v.y = vals[q+1]*inv;
                v.z = vals[q+2]*inv; v.w = vals[q+3]*inv;
                *(float4*)(op + q) = v;
            }
        }
    }
    __syncthreads();
    if (tid == 0) {
        #pragma unroll
        for (int s = 0; s < ANST; s++) {
            asm volatile("mbarrier.inval.shared.b64 [%0];" :: "r"(sbase + MB_FULL(s)) : "memory");
            asm volatile("mbarrier.inval.shared.b64 [%0];" :: "r"(sbase + MB_EMPTY(s)) : "memory");
        }
        asm volatile("mbarrier.inval.shared.b64 [%0];" :: "r"(sbase + MB_DONE) : "memory");
    }
    __syncthreads();
    if (wid == 0) {
        asm volatile("tcgen05.dealloc.cta_group::1.sync.aligned.b32 %0, %1;"
                     :: "r"(tmem), "r"(128u));
    }

#else
    (void)tmap;
    if (tid == 0) {
        const float tv = temp[bh % Hh];
        const __half* T = g_qkT + (size_t)bh * 128 * Nn;
        float normv[128];
        for (int i = 0; i < 128; i++) {
            double s = 0;
            for (int n = 0; n < Nn; n++) {
                float v = __half2float(T[(size_t)i*Nn+n]); s += (double)v*v;
            }
            normv[i] = fmaxf(sqrtf((float)s), 1e-12f);
        }
        for (int p = 0; p < 64; p++) {
            float vals[64]; float m = -1e30f;
            for (int q = 0; q < 64; q++) {
                double s = 0;
                for (int n = 0; n < Nn; n++)
                    s += (double)__half2float(T[(size_t)p*Nn+n]) *
                         (double)__half2float(T[(size_t)(64+q)*Nn+n]);
                vals[q] = (float)s * tv / (normv[p] * normv[64+q]);
                m = fmaxf(m, vals[q]);
            }
            float s = 0;
            for (int q = 0; q < 64; q++) { vals[q] = expf(vals[q]-m); s += vals[q]; }
            for (int q = 0; q < 64; q++)
                g_attn[(size_t)bh*4096 + p*64 + q] = vals[q] / s;
        }
    }
#endif
}

// ---------------------------------------------------------------------------
// fp32 -> fp16 (elementwise, rn)
// ---------------------------------------------------------------------------
__global__ __launch_bounds__(256) void half_kernel(
    const float* __restrict__ in, __half* __restrict__ outp, size_t n4)
{
    const size_t i = (size_t)blockIdx.x * blockDim.x + threadIdx.x;
    if (i >= n4) return;
    float4 v = ((const float4*)in)[i];
    __half2 h0 = __floats2half2_rn(v.x, v.y);
    __half2 h1 = __floats2half2_rn(v.z, v.w);
    ((__half2*)outp)[2*i]   = h0;
    ((__half2*)outp)[2*i+1] = h1;
}

// ---------------------------------------------------------------------------
// W [K,N] fp32 -> transposed fp16 [N,K] row-major
// ---------------------------------------------------------------------------
__global__ __launch_bounds__(256) void transpose_half(
    const float* __restrict__ W, __half* __restrict__ o, int K, int N)
{
    __shared__ float t[32][33];
    const int n0 = blockIdx.x * 32, k0 = blockIdx.y * 32;
    const int tx = threadIdx.x & 31, ty = threadIdx.x >> 5;
    #pragma unroll
    for (int i = ty; i < 32; i += 8)
        t[i][tx] = W[(size_t)(k0 + i) * N + n0 + tx];
    __syncthreads();
    #pragma unroll
    for (int i = ty; i < 32; i += 8)
        o[(size_t)(n0 + i) * K + k0 + tx] = __float2half_rn(t[tx][i]);
}

// ---------------------------------------------------------------------------
// out[b,h,n,q] = sum_p v[n,p] attn[p,q]  -> fp16, row-major [Mrows x 768]
// v read from g_vh fp16.
// ---------------------------------------------------------------------------
__global__ __launch_bounds__(256) void av_kernel()
{
    const int bh = blockIdx.x;
    const int nt = blockIdx.y;
    const int b  = bh / Hh, h = bh % Hh;
    const int tid = threadIdx.x;
    const int tx = tid & 15, ty = tid >> 4;

    __shared__ float At[64][68];
    __shared__ float Vs[64][68];

    {
        const float* ap = g_attn + (size_t)bh * 4096;
        #pragma unroll
        for (int pp = 0; pp < 4; pp++) {
            const int idx = pp * 1024 + tid * 4;
            *(float4*)&At[idx >> 6][idx & 63] = *(const float4*)(ap + idx);
        }
    }
    const int lr = tid >> 4, lc = (tid & 15) * 4;
    const int voff = h * dh;
    const size_t rowbase = (size_t)b * Nn + nt * 64;
    #pragma unroll
    for (int pp = 0; pp < 64; pp += 16) {
        // 4 fp16 per thread: 8B load
        const __half* vp = g_vh + (rowbase + pp + lr) * Dd + voff + lc;
        __half2 a = *(const __half2*)(vp);
        __half2 bv = *(const __half2*)(vp + 2);
        Vs[pp + lr][lc + 0] = __half2float(__low2half(a));
        Vs[pp + lr][lc + 1] = __half2float(__high2half(a));
        Vs[pp + lr][lc + 2] = __half2float(__low2half(bv));
        Vs[pp + lr][lc + 3] = __half2float(__high2half(bv));
    }
    __syncthreads();

    float acc[4][4];
    #pragma unroll
    for (int i = 0; i < 4; i++)
        #pragma unroll
        for (int j = 0; j < 4; j++) acc[i][j] = 0.f;

    #pragma unroll 8
    for (int p = 0; p < 64; p++) {
        float ra[4];
        *(float4*)ra = *(const float4*)&At[p][tx * 4];
        float rv[4];
        #pragma unroll
        for (int i = 0; i < 4; i++) rv[i] = Vs[ty * 4 + i][p];
        #pragma unroll
        for (int i = 0; i < 4; i++)
            #pragma unroll
            for (int j = 0; j < 4; j++)
                acc[i][j] = fmaf(rv[i], ra[j], acc[i][j]);
    }

    #pragma unroll
    for (int i = 0; i < 4; i++) {
        const size_t r = rowbase + ty * 4 + i;
        __half2 h0 = __floats2half2_rn(acc[i][0], acc[i][1]);
        __half2 h1 = __floats2half2_rn(acc[i][2], acc[i][3]);
        __half* op = g_oatth + r * Dd + h * dh + tx * 4;
        *(__half2*)(op)     = h0;
        *(__half2*)(op + 2) = h1;
    }
}

// ---------------------------------------------------------------------------
// host: tensormap construction via driver entry point (no -lcuda needed)
// ---------------------------------------------------------------------------
typedef CUresult (*EncodeTiledFn)(
    CUtensorMap*, CUtensorMapDataType, cuuint32_t, void*,
    const cuuint64_t*, const cuuint64_t*, const cuuint32_t*, const cuuint32_t*,
    CUtensorMapInterleave, CUtensorMapSwizzle, CUtensorMapL2promotion,
    CUtensorMapFloatOOBfill);

static void encode_map16(EncodeTiledFn enc, CUtensorMap* m, void* base,
                         unsigned long long cols, unsigned long long nrows,
                         unsigned boxrows)
{
    cuuint64_t dims[2]    = {cols, nrows};
    cuuint64_t strides[1] = {cols * 2};                // fp16
    cuuint32_t box[2]     = {64u, boxrows};            // 128B x boxrows
    cuuint32_t estr[2]    = {1u, 1u};
    enc(m, CU_TENSOR_MAP_DATA_TYPE_FLOAT16, 2, base, dims, strides, box, estr,
        CU_TENSOR_MAP_INTERLEAVE_NONE, CU_TENSOR_MAP_SWIZZLE_128B,
        CU_TENSOR_MAP_L2_PROMOTION_L2_128B, CU_TENSOR_MAP_FLOAT_OOB_FILL_NONE);
}

extern "C" void kernel_launch(void* const* d_in, const int* in_sizes, int n_in,
                              void* d_out, int out_size)
{
    const float* x     = (const float*)d_in[0];
    const float* Wqkv  = (const float*)d_in[1];
    const float* temp  = (const float*)d_in[2];
    const float* Wout  = (const float*)d_in[3];
    const float* bout  = (const float*)d_in[4];
    float* out = (float*)d_out;

    __half *xh, *wth, *woth, *oatth, *qkT, *vh;
    cudaGetSymbolAddress((void**)&xh,    g_xh);
    cudaGetSymbolAddress((void**)&wth,   g_wth);
    cudaGetSymbolAddress((void**)&woth,  g_woth);
    cudaGetSymbolAddress((void**)&oatth, g_oatth);
    cudaGetSymbolAddress((void**)&qkT,   g_qkT);
    cudaGetSymbolAddress((void**)&vh,    g_vh);
    CUtensorMap* dmaps;
    cudaGetSymbolAddress((void**)&dmaps, g_tmaps);

    static CUtensorMap h_tmaps[5];
    static EncodeTiledFn enc = nullptr;
    if (!enc) {
        void* p = nullptr;
        cudaDriverEntryPointQueryResult st;
        cudaGetDriverEntryPoint("cuTensorMapEncodeTiled", &p, cudaEnableDefault, &st);
        enc = (EncodeTiledFn)p;
    }
    encode_map16(enc, &h_tmaps[0], xh,    GK, (unsigned long long)Mrows, 256);
    encode_map16(enc, &h_tmaps[1], wth,   GK, (unsigned long long)QKVC, 128);
    encode_map16(enc, &h_tmaps[2], oatth, GK, (unsigned long long)Mrows, 256);
    encode_map16(enc, &h_tmaps[3], woth,  GK, (unsigned long long)Dd,   128);
    encode_map16(enc, &h_tmaps[4], qkT,   Nn, (unsigned long long)(Bc*Hh*128), 128);
    cudaMemcpyToSymbolAsync(g_tmaps, h_tmaps, sizeof(h_tmaps), 0,
                            cudaMemcpyHostToDevice, 0);

    cudaFuncSetAttribute(gemm_f16, cudaFuncAttributeMaxDynamicSharedMemorySize, GEMM_SMEM);
    cudaFuncSetAttribute(attn_tc,  cudaFuncAttributeMaxDynamicSharedMemorySize, ATTN_SMEM);

    // 1) x -> fp16; transpose weights -> fp16
    {
        size_t n4 = (size_t)Mrows * Dd / 4;
        half_kernel<<<(unsigned)((n4 + 255) / 256), 256>>>(x, xh, n4);
    }
    transpose_half<<<dim3(QKVC/32, Dd/32), 256>>>(Wqkv, wth, Dd, QKVC);
    transpose_half<<<dim3(Dd/32,  Dd/32), 256>>>(Wout, woth, Dd, Dd);

    // 2) qkv = x @ Wqkv; q,k transposed fp16 -> g_qkT, v fp16 -> g_vh
    gemm_f16<<<dim3(QKVC/NT, Mrows/MT), 256, GEMM_SMEM>>>(
        dmaps + 0, xh, wth, nullptr, QKVC, nullptr, qkT, vh);

    // 3) attention via tcgen05: D = [k;q][k;q]^T -> norms + softmax
    attn_tc<<<dim3(Bc * Hh), 128, ATTN_SMEM>>>(dmaps + 4, temp);

    // 4) out = v @ attn  (fp16 in, fp16 out)
    av_kernel<<<dim3(Bc * Hh, Nn / 64), 256>>>();

    // 5) final projection + bias -> fp32 out
    gemm_f16<<<dim3(Dd/NT, Mrows/MT), 256, GEMM_SMEM>>>(
        dmaps + 2, oatth, woth, out, Dd, bout, nullptr, nullptr);
}

// round 16
// speedup vs baseline: 1.4282x; 1.0401x over previous
#include <cuda_runtime.h>
#include <cuda.h>
#include <cuda_fp16.h>
#include <math.h>
#include <stdint.h>

#define Bc 8
#define Nn 4096
#define Dd 768
#define Hh 12
#define dh 64
#define Mrows (Bc*Nn)      /* 32768 */
#define QKVC  (3*Dd)       /* 2304  */
#define GK    Dd           /* GEMM K = 768 */

// ---------------- scratch (device globals; allocation-free rule) -----------
__device__ float g_attn[Bc*Hh*dh*dh];                        // 1.5 MB
__device__ __align__(256) __half g_qkT[(size_t)Bc*Hh*128*Nn];  // 100 MB [bh][128][4096]
__device__ __align__(256) __half g_vh[(size_t)Mrows*Dd];       // 50 MB  v fp16
__device__ __align__(256) __half g_xh[(size_t)Mrows*Dd];       // x fp16
__device__ __align__(256) __half g_wth[(size_t)QKVC*Dd];       // Wqkv^T [N,K] fp16
__device__ __align__(256) __half g_woth[(size_t)Dd*Dd];        // Wout^T [N,K] fp16
__device__ __align__(256) __half g_oatth[(size_t)Mrows*Dd];    // v@attn fp16
// tensormaps: [0]=xh(A1), [1]=wth(B1), [2]=oatth(A2), [3]=woth(B2), [4]=qkT
__device__ __align__(128) CUtensorMap g_tmaps[5];

// ---------------- arch feature gate -----------------------------------------
#if defined(__CUDA_ARCH_FEAT_SM103_ALL) || defined(__CUDA_ARCH_FEAT_SM100_ALL) || defined(__CUDA_ARCH_FEAT_SM101_ALL)
#define HAS_TCG 1
#else
#define HAS_TCG 0
#endif

// ---------------- common helpers --------------------------------------------
__device__ __forceinline__ uint32_t smem_u32(const void* p){
    uint32_t a;
    asm("{ .reg .u64 t; cvta.to.shared.u64 t, %1; cvt.u32.u64 %0, t; }" : "=r"(a) : "l"(p));
    return a;
}

// ---------------- GEMM tile geometry (fp16) ----------------------------------
#define MT 256
#define NT 256
#define KCH 64                  /* K elems per chunk: 64 fp16 = 128B rows */
#define NCH (GK/KCH)            /* 12 */
#define NSTAGE 3
#define OA 0                    /* A tile 256x64 fp16 = 32KB (M halves +16K) */
#define OB 32768                /* B tile 256x64 fp16 = 32KB (mc halves +16K) */
#define STAGE_BYTES 65536
#define SM_TILE0 1024
#define GEMM_SMEM (SM_TILE0 + NSTAGE*STAGE_BYTES) /* 197632 */

// attn_tc geometry (fp16)
#define ACH 64                  /* n per chunk: 64 fp16 = 128B rows */
#define ANCH (Nn/ACH)           /* 64 */
#define ANST 6
#define ASTAGE_BYTES 16384      /* 128 rows x 128B */
#define ATTN_SMEM (SM_TILE0 + ANST*ASTAGE_BYTES)  /* 99328 */

#if HAS_TCG
// ---------------- tcgen05 / TMA helpers (arch-specific pass only) -----------
__device__ __forceinline__ uint32_t elect1(){
    uint32_t p;
    asm volatile("{\n\t.reg .pred p;\n\telect.sync _|p, 0xFFFFFFFF;\n\tselp.b32 %0, 1, 0, p;\n\t}" : "=r"(p));
    return p;
}
__device__ __forceinline__ uint32_t ctarank(){
    uint32_t r;
    asm("mov.u32 %0, %%cluster_ctarank;" : "=r"(r));
    return r;
}
// SW128 K-major descriptor: layout=2, version=1, SBO=64, LBO=1 (128B rows)
static constexpr uint64_t DESC_BASE_SW128 =
    (uint64_t(2) << 61) | (uint64_t(1) << 46) | (uint64_t(64) << 32) | (uint64_t(1) << 16);
#define MK128(a) (DESC_BASE_SW128 | ((uint64_t)((a) >> 4) & 0x3FFF))
// idesc fp16 (atype=btype=0), F32 accum (1<<4), M=128 (8<<24)
#define IDESC_N256 0x8400010u
#define IDESC_N128 0x8200010u

__device__ __forceinline__ void mma_f16_ss(uint32_t d, uint64_t a, uint64_t b,
                                           uint32_t idesc, uint32_t en){
    asm volatile(
        "{\n\t.reg .pred p;\n\tsetp.ne.u32 p, %3, 0;\n\t"
        "tcgen05.mma.cta_group::1.kind::f16 [%0], %1, %2, %4, {%5,%5,%5,%5}, p;\n\t}"
        :: "r"(d), "l"(a), "l"(b), "r"(en), "r"(idesc), "r"(0u) : "memory");
}
__device__ __forceinline__ void tc_commit(uint32_t mbar){
    asm volatile("tcgen05.commit.cta_group::1.mbarrier::arrive::one.shared::cluster.b64 [%0];"
                 :: "r"(mbar) : "memory");
}
__device__ __forceinline__ void tc_commit_mc(uint32_t mbar, uint16_t mask){
    asm volatile("tcgen05.commit.cta_group::1.mbarrier::arrive::one.shared::cluster.multicast::cluster.b64 [%0], %1;"
                 :: "r"(mbar), "h"(mask) : "memory");
}
__device__ __forceinline__ void mbar_init(uint32_t mbar, uint32_t cnt){
    asm volatile("mbarrier.init.shared.b64 [%0], %1;" :: "r"(mbar), "r"(cnt) : "memory");
}
__device__ __forceinline__ void mbar_wait(uint32_t mbar, uint32_t parity){
    asm volatile(
        "{\n\t.reg .pred P;\n\tWL_%=:\n\t"
        "mbarrier.try_wait.parity.acquire.cta.shared::cta.b64 P, [%0], %1, 0x989680;\n\t"
        "@P bra.uni WD_%=;\n\tbra.uni WL_%=;\n\tWD_%=:\n\t}"
        :: "r"(mbar), "r"(parity) : "memory");
}
__device__ __forceinline__ void mbar_wait_rlx(uint32_t mbar, uint32_t parity){
    asm volatile(
        "{\n\t.reg .pred P;\n\tWL_%=:\n\t"
        "mbarrier.try_wait.parity.relaxed.cta.shared::cta.b64 P, [%0], %1, 0x989680;\n\t"
        "@P bra.uni WD_%=;\n\tbra.uni WL_%=;\n\tWD_%=:\n\t}"
        :: "r"(mbar), "r"(parity) : "memory");
}
#define EXPECT_TX(mbar, bytes) \
    asm volatile("mbarrier.arrive.expect_tx.shared.b64 _, [%0], %1;" \
                 :: "r"(mbar), "r"((uint32_t)(bytes)) : "memory")
#define TMA2D(smem, map, x, y, mbar) \
    asm volatile("cp.async.bulk.tensor.2d.shared::cta.global.tile.mbarrier::complete_tx::bytes " \
                 "[%0], [%1, {%2, %3}], [%4];" \
                 :: "r"((uint32_t)(smem)), "l"(map), "r"((int)(x)), "r"((int)(y)), \
                    "r"((uint32_t)(mbar)) : "memory")
#define TMA2D_MC(smem, map, x, y, mbar, mask) \
    asm volatile("cp.async.bulk.tensor.2d.shared::cluster.global.tile.mbarrier::complete_tx::bytes.multicast::cluster " \
                 "[%0], [%1, {%2, %3}], [%4], %5;" \
                 :: "r"((uint32_t)(smem)), "l"(map), "r"((int)(x)), "r"((int)(y)), \
                    "r"((uint32_t)(mbar)), "h"((uint16_t)(mask)) : "memory")
#define CLUSTER_SYNC() do { \
    asm volatile("barrier.cluster.arrive.aligned;" ::: "memory"); \
    asm volatile("barrier.cluster.wait.aligned;" ::: "memory"); \
} while(0)

#define TC_FENCE_AFTER()  asm volatile("tcgen05.fence::after_thread_sync;" ::: "memory")
#define TC_FENCE_BEFORE() asm volatile("tcgen05.fence::before_thread_sync;" ::: "memory")
#define TC_WAIT_LD() asm volatile("tcgen05.wait::ld.sync.aligned;" ::: "memory")

#define LDTM32(r, addr) \
    asm volatile( \
        "tcgen05.ld.sync.aligned.32x32b.x32.b32 " \
        "{%0, %1, %2, %3, %4, %5, %6, %7, " \
        " %8, %9, %10, %11, %12, %13, %14, %15, " \
        " %16, %17, %18, %19, %20, %21, %22, %23, " \
        " %24, %25, %26, %27, %28, %29, %30, %31}, [%32];" \
        : "=r"((r)[0]),  "=r"((r)[1]),  "=r"((r)[2]),  "=r"((r)[3]), \
          "=r"((r)[4]),  "=r"((r)[5]),  "=r"((r)[6]),  "=r"((r)[7]), \
          "=r"((r)[8]),  "=r"((r)[9]),  "=r"((r)[10]), "=r"((r)[11]), \
          "=r"((r)[12]), "=r"((r)[13]), "=r"((r)[14]), "=r"((r)[15]), \
          "=r"((r)[16]), "=r"((r)[17]), "=r"((r)[18]), "=r"((r)[19]), \
          "=r"((r)[20]), "=r"((r)[21]), "=r"((r)[22]), "=r"((r)[23]), \
          "=r"((r)[24]), "=r"((r)[25]), "=r"((r)[26]), "=r"((r)[27]), \
          "=r"((r)[28]), "=r"((r)[29]), "=r"((r)[30]), "=r"((r)[31]) \
        : "r"(addr))
#endif  // HAS_TCG

// smem control offsets
#define MB_FULL(s)  (8  + (s)*8)
#define MB_EMPTY(s) (64 + (s)*8)
#define MB_DONE     120
#define SO_NORM     256              /* attn_tc: float norm[128] at +256 */

// ---------------------------------------------------------------------------
// fp16 tcgen05 GEMM:  C = A[M,GK] * B^T  (A,B fp16 K-major row-major)
// GEMM1 mode (qkT/vh non-null): q,k transposed via SMEM-staged coalesced
// stores; v written fp16 row-major. GEMM2 mode: fp32 C + bias.
// ---------------------------------------------------------------------------
__global__ __launch_bounds__(256) __cluster_dims__(1, 2, 1)
void gemm_f16(
    const CUtensorMap* __restrict__ tmaps,   // [A, B]
    const __half* __restrict__ A, const __half* __restrict__ B,
    float* __restrict__ C, int Ntot, const float* __restrict__ bias,
    __half* __restrict__ qkT, __half* __restrict__ vh)
{
    const int tid = threadIdx.x;
    const int row0 = blockIdx.y * MT;
    const int col0 = blockIdx.x * NT;

#if HAS_TCG
    extern __shared__ char smem[];
    const uint32_t sbase = smem_u32(smem);
    const int wid = tid >> 5;
    const int lane = tid & 31;
    const uint32_t rank = ctarank();

    if (wid == 0) {
        asm volatile("tcgen05.alloc.cta_group::1.sync.aligned.shared::cta.b32 [%0], %1;"
                     :: "r"(sbase), "r"(512u) : "memory");
    }
    if (tid == 0) {
        #pragma unroll
        for (int s = 0; s < NSTAGE; s++) {
            mbar_init(sbase + MB_FULL(s), 1);
            mbar_init(sbase + MB_EMPTY(s), 2);
        }
        mbar_init(sbase + MB_DONE, 1);
    }
    __syncthreads();
    uint32_t tmem;
    asm volatile("ld.shared.b32 %0, [%1];" : "=r"(tmem) : "r"(sbase));
    if (wid == 0)
        asm volatile("tcgen05.relinquish_alloc_permit.cta_group::1.sync.aligned;");

    CLUSTER_SYNC();

    uint32_t leader = 0, producer = 0;
    if (wid == 0) leader = elect1();
    if (wid == 1) producer = elect1();

    if (producer) {
        for (int ch = 0; ch < NCH; ch++) {
            const int st = ch % NSTAGE;
            const uint32_t sb = sbase + SM_TILE0 + st*STAGE_BYTES;
            if (ch >= NSTAGE)
                mbar_wait_rlx(sbase + MB_EMPTY(st), ((ch - NSTAGE) / NSTAGE) & 1);
            EXPECT_TX(sbase + MB_FULL(st), 65536u);
            TMA2D(sb + OA, tmaps + 0, ch*KCH, row0, sbase + MB_FULL(st));
            TMA2D_MC(sb + OB + rank*16384, tmaps + 1, ch*KCH,
                     col0 + (int)rank*128, sbase + MB_FULL(st), 3);
        }
    }

    if (leader) {
        uint32_t first = 0;
        const uint32_t tm0 = tmem, tm1 = tmem + 256;
        for (int ch = 0; ch < NCH; ch++) {
            const int st = ch % NSTAGE;
            mbar_wait(sbase + MB_FULL(st), (ch / NSTAGE) & 1);
            const uint32_t sb = sbase + SM_TILE0 + st*STAGE_BYTES;
            const uint64_t dA0 = MK128(sb + OA);
            const uint64_t dA1 = MK128(sb + OA + 16384);
            const uint64_t dB  = MK128(sb + OB);
            #pragma unroll
            for (int k = 0; k < 4; k++) {      // K=16 per f16 MMA; 4 k-steps
                const uint64_t o = k*2;        // 32B per k-step
                mma_f16_ss(tm0, dA0 + o, dB + o, IDESC_N256, first);
                mma_f16_ss(tm1, dA1 + o, dB + o, IDESC_N256, first);
                first = 1;
            }
            tc_commit_mc(sbase + MB_EMPTY(st), 3);
        }
        tc_commit(sbase + MB_DONE);
    }

    mbar_wait(sbase + MB_DONE, 0);
    TC_FENCE_AFTER();

    // ---- epilogue ----
    {
        const int mh = wid >> 2;
        const int rr = mh*128 + (wid & 3)*32 + lane;   // CTA-local row 0..255
        const int r  = row0 + rr;
        const uint32_t tb = tmem + mh*256;
        const bool g1 = (qkT != nullptr);

        if (g1 && col0 < 1536) {
            // q/k tile: SMEM-staged transpose, coalesced STG.128 writes.
            // stage buffers are dead after MMA drain; reuse as [32][264] fp16.
            __half* sT = (__half*)(smem + SM_TILE0);
            const int bb2 = row0 >> 12;        // batch (row0 256-aligned, Nn%256==0)
            const int n0v = row0 & 4095;       // n offset
            #pragma unroll
            for (int chk = 0; chk < 8; chk++) {
                uint32_t regs[32];
                LDTM32(regs, tb + chk*32);
                TC_WAIT_LD();
                #pragma unroll
                for (int j = 0; j < 32; j++)
                    sT[j*264 + rr] = __float2half_rn(__uint_as_float(regs[j]));
                __syncthreads();
                #pragma unroll
                for (int it = 0; it < 4; it++) {
                    const int col = it*8 + wid;
                    const int c = col0 + chk*32 + col;
                    const int cc = (c < 768) ? c : c - 768;
                    const int qrow = (bb2*Hh + (cc >> 6))*128
                                     + ((c < 768) ? 64 : 0) + (cc & 63);
                    float4 val = *(float4*)&sT[col*264 + lane*8];
                    *(float4*)(qkT + (size_t)qrow * Nn + n0v + lane*8) = val;
                }
                __syncthreads();
            }
        } else if (g1) {
            // v tile -> fp16 row-major [Mrows x 768]
            #pragma unroll
            for (int chk = 0; chk < 8; chk++) {
                uint32_t regs[32];
                LDTM32(regs, tb + chk*32);
                TC_WAIT_LD();
                const int c0 = col0 + chk*32;
                __half* vrow = vh + (size_t)r * Dd + (c0 - 1536);
                #pragma unroll
                for (int j = 0; j < 32; j += 2) {
                    __half2 hv = __floats2half2_rn(
                        __uint_as_float(regs[j]), __uint_as_float(regs[j+1]));
                    *(__half2*)(vrow + j) = hv;
                }
            }
        } else {
            float* crow = C + (size_t)r * Ntot;
            #pragma unroll
            for (int chk = 0; chk < 8; chk++) {
                uint32_t regs[32];
                LDTM32(regs, tb + chk*32);
                TC_WAIT_LD();
                const int c0 = col0 + chk*32;
                #pragma unroll
                for (int j = 0; j < 32; j += 4) {
                    float4 v;
                    v.x = __uint_as_float(regs[j+0]);
                    v.y = __uint_as_float(regs[j+1]);
                    v.z = __uint_as_float(regs[j+2]);
                    v.w = __uint_as_float(regs[j+3]);
                    if (bias) {
                        v.x += bias[c0+j+0]; v.y += bias[c0+j+1];
                        v.z += bias[c0+j+2]; v.w += bias[c0+j+3];
                    }
                    *(float4*)(crow + c0 + j) = v;
                }
            }
        }
        TC_FENCE_BEFORE();
    }
    __syncthreads();
    CLUSTER_SYNC();
    if (tid == 0) {
        #pragma unroll
        for (int s = 0; s < NSTAGE; s++) {
            asm volatile("mbarrier.inval.shared.b64 [%0];" :: "r"(sbase + MB_FULL(s)) : "memory");
            asm volatile("mbarrier.inval.shared.b64 [%0];" :: "r"(sbase + MB_EMPTY(s)) : "memory");
        }
        asm volatile("mbarrier.inval.shared.b64 [%0];" :: "r"(sbase + MB_DONE) : "memory");
    }
    __syncthreads();
    if (wid == 0) {
        asm volatile("tcgen05.dealloc.cta_group::1.sync.aligned.b32 %0, %1;"
                     :: "r"(tmem), "r"(512u));
    }
    CLUSTER_SYNC();

#else
    (void)tmaps;
    for (int idx = tid; idx < MT*NT; idx += 256) {
        const int r = row0 + idx / NT;
        const int c = col0 + idx % NT;
        float s = bias ? bias[c] : 0.f;
        for (int k = 0; k < GK; k++)
            s = fmaf(__half2float(A[(size_t)r * GK + k]),
                     __half2float(B[(size_t)c * GK + k]), s);
        if (qkT) {
            if (c < 1536) {
                const int bb = r >> 12, nn = r & 4095;
                const int cc = (c < 768) ? c : c - 768;
                const int qrow = (bb*Hh + (cc >> 6))*128 + ((c < 768) ? 64 : 0) + (cc & 63);
                qkT[(size_t)qrow * Nn + nn] = __float2half_rn(s);
            } else {
                vh[(size_t)r * Dd + (c - 1536)] = __float2half_rn(s);
            }
        } else {
            C[(size_t)r * Ntot + c] = s;
        }
    }
#endif
}

// ---------------------------------------------------------------------------
// attn_tc: per (b,h), D[128x128] = T T^T over n (T = [k;q] fp16, 128 x 4096),
// then norms from diag, temperature, softmax -> g_attn. grid 96, block 128.
// ---------------------------------------------------------------------------
__global__ __launch_bounds__(128) void attn_tc(
    const CUtensorMap* __restrict__ tmap, const float* __restrict__ temp)
{
    const int bh = blockIdx.x;
    const int tid = threadIdx.x;

#if HAS_TCG
    extern __shared__ char smem[];
    const uint32_t sbase = smem_u32(smem);
    const int wid = tid >> 5;
    const int lane = tid & 31;

    if (wid == 0) {
        asm volatile("tcgen05.alloc.cta_group::1.sync.aligned.shared::cta.b32 [%0], %1;"
                     :: "r"(sbase), "r"(128u) : "memory");
    }
    if (tid == 0) {
        #pragma unroll
        for (int s = 0; s < ANST; s++) {
            mbar_init(sbase + MB_FULL(s), 1);
            mbar_init(sbase + MB_EMPTY(s), 1);
        }
        mbar_init(sbase + MB_DONE, 1);
    }
    __syncthreads();
    uint32_t tmem;
    asm volatile("ld.shared.b32 %0, [%1];" : "=r"(tmem) : "r"(sbase));
    if (wid == 0)
        asm volatile("tcgen05.relinquish_alloc_permit.cta_group::1.sync.aligned;");
    __syncthreads();

    uint32_t leader = 0, producer = 0;
    if (wid == 0) leader = elect1();
    if (wid == 1) producer = elect1();

    if (producer) {
        for (int ch = 0; ch < ANCH; ch++) {
            const int st = ch % ANST;
            const uint32_t sb = sbase + SM_TILE0 + st*ASTAGE_BYTES;
            if (ch >= ANST)
                mbar_wait_rlx(sbase + MB_EMPTY(st), ((ch - ANST) / ANST) & 1);
            EXPECT_TX(sbase + MB_FULL(st), 16384u);
            TMA2D(sb, tmap, ch*ACH, bh*128, sbase + MB_FULL(st));
        }
    }

    if (leader) {
        uint32_t first = 0;
        for (int ch = 0; ch < ANCH; ch++) {
            const int st = ch % ANST;
            mbar_wait(sbase + MB_FULL(st), (ch / ANST) & 1);
            const uint64_t dT = MK128(sbase + SM_TILE0 + st*ASTAGE_BYTES);
            #pragma unroll
            for (int k = 0; k < 4; k++) {
                mma_f16_ss(tmem, dT + k*2, dT + k*2, IDESC_N128, first);
                first = 1;
            }
            tc_commit(sbase + MB_EMPTY(st));
        }
        tc_commit(sbase + MB_DONE);
    }

    mbar_wait(sbase + MB_DONE, 0);
    TC_FENCE_AFTER();

    {
        const int r = wid*32 + lane;
        uint32_t regs[128];
        #pragma unroll
        for (int chk = 0; chk < 4; chk++) {
            LDTM32(regs + chk*32, tmem + chk*32);
        }
        TC_WAIT_LD();
        TC_FENCE_BEFORE();

        float* normp = (float*)(smem + SO_NORM);
        normp[r] = fmaxf(sqrtf(__uint_as_float(regs[r])), 1e-12f);
        __syncthreads();

        if (r < 64) {
            const float tv = temp[bh % Hh];
            const float nk = normp[r];
            float vals[64];
            float m = -1e30f;
            #pragma unroll
            for (int q = 0; q < 64; q++) {
                vals[q] = __uint_as_float(regs[64+q]) * tv / (nk * normp[64+q]);
                m = fmaxf(m, vals[q]);
            }
            float s = 0.f;
            #pragma unroll
            for (int q = 0; q < 64; q++) { vals[q] = expf(vals[q] - m); s += vals[q]; }
            const float inv = 1.f / s;
            float* op = g_attn + (size_t)bh * 4096 + r * 64;
            #pragma unroll
            for (int q = 0; q < 64; q += 4) {
                float4 v;
                v.x = vals[q+0]*inv; v.y = vals[q+1]*inv;
                v.z = vals[q+2]*inv; v.w = vals[q+3]*inv;
                *(float4*)(op + q) = v;
            }
        }
    }
    __syncthreads();
    if (tid == 0) {
        #pragma unroll
        for (int s = 0; s < ANST; s++) {
            asm volatile("mbarrier.inval.shared.b64 [%0];" :: "r"(sbase + MB_FULL(s)) : "memory");
            asm volatile("mbarrier.inval.shared.b64 [%0];" :: "r"(sbase + MB_EMPTY(s)) : "memory");
        }
        asm volatile("mbarrier.inval.shared.b64 [%0];" :: "r"(sbase + MB_DONE) : "memory");
    }
    __syncthreads();
    if (wid == 0) {
        asm volatile("tcgen05.dealloc.cta_group::1.sync.aligned.b32 %0, %1;"
                     :: "r"(tmem), "r"(128u));
    }

#else
    (void)tmap;
    if (tid == 0) {
        const float tv = temp[bh % Hh];
        const __half* T = g_qkT + (size_t)bh * 128 * Nn;
        float normv[128];
        for (int i = 0; i < 128; i++) {
            double s = 0;
            for (int n = 0; n < Nn; n++) {
                float v = __half2float(T[(size_t)i*Nn+n]); s += (double)v*v;
            }
            normv[i] = fmaxf(sqrtf((float)s), 1e-12f);
        }
        for (int p = 0; p < 64; p++) {
            float vals[64]; float m = -1e30f;
            for (int q = 0; q < 64; q++) {
                double s = 0;
                for (int n = 0; n < Nn; n++)
                    s += (double)__half2float(T[(size_t)p*Nn+n]) *
                         (double)__half2float(T[(size_t)(64+q)*Nn+n]);
                vals[q] = (float)s * tv / (normv[p] * normv[64+q]);
                m = fmaxf(m, vals[q]);
            }
            float s = 0;
            for (int q = 0; q < 64; q++) { vals[q] = expf(vals[q]-m); s += vals[q]; }
            for (int q = 0; q < 64; q++)
                g_attn[(size_t)bh*4096 + p*64 + q] = vals[q] / s;
        }
    }
#endif
}

// ---------------------------------------------------------------------------
// fp32 -> fp16 (elementwise, rn)
// ---------------------------------------------------------------------------
__global__ __launch_bounds__(256) void half_kernel(
    const float* __restrict__ in, __half* __restrict__ outp, size_t n4)
{
    const size_t i = (size_t)blockIdx.x * blockDim.x + threadIdx.x;
    if (i >= n4) return;
    float4 v = ((const float4*)in)[i];
    __half2 h0 = __floats2half2_rn(v.x, v.y);
    __half2 h1 = __floats2half2_rn(v.z, v.w);
    ((__half2*)outp)[2*i]   = h0;
    ((__half2*)outp)[2*i+1] = h1;
}

// ---------------------------------------------------------------------------
// W [K,N] fp32 -> transposed fp16 [N,K] row-major
// ---------------------------------------------------------------------------
__global__ __launch_bounds__(256) void transpose_half(
    const float* __restrict__ W, __half* __restrict__ o, int K, int N)
{
    __shared__ float t[32][33];
    const int n0 = blockIdx.x * 32, k0 = blockIdx.y * 32;
    const int tx = threadIdx.x & 31, ty = threadIdx.x >> 5;
    #pragma unroll
    for (int i = ty; i < 32; i += 8)
        t[i][tx] = W[(size_t)(k0 + i) * N + n0 + tx];
    __syncthreads();
    #pragma unroll
    for (int i = ty; i < 32; i += 8)
        o[(size_t)(n0 + i) * K + k0 + tx] = __float2half_rn(t[tx][i]);
}

// ---------------------------------------------------------------------------
// out[b,h,n,q] = sum_p v[n,p] attn[p,q]  -> fp16, row-major [Mrows x 768]
// ---------------------------------------------------------------------------
__global__ __launch_bounds__(256) void av_kernel()
{
    const int bh = blockIdx.x;
    const int nt = blockIdx.y;
    const int b  = bh / Hh, h = bh % Hh;
    const int tid = threadIdx.x;
    const int tx = tid & 15, ty = tid >> 4;

    __shared__ float At[64][68];
    __shared__ float Vs[64][68];

    {
        const float* ap = g_attn + (size_t)bh * 4096;
        #pragma unroll
        for (int pp = 0; pp < 4; pp++) {
            const int idx = pp * 1024 + tid * 4;
            *(float4*)&At[idx >> 6][idx & 63] = *(const float4*)(ap + idx);
        }
    }
    const int lr = tid >> 4, lc = (tid & 15) * 4;
    const int voff = h * dh;
    const size_t rowbase = (size_t)b * Nn + nt * 64;
    #pragma unroll
    for (int pp = 0; pp < 64; pp += 16) {
        const __half* vp = g_vh + (rowbase + pp + lr) * Dd + voff + lc;
        __half2 a = *(const __half2*)(vp);
        __half2 bv = *(const __half2*)(vp + 2);
        Vs[pp + lr][lc + 0] = __half2float(__low2half(a));
        Vs[pp + lr][lc + 1] = __half2float(__high2half(a));
        Vs[pp + lr][lc + 2] = __half2float(__low2half(bv));
        Vs[pp + lr][lc + 3] = __half2float(__high2half(bv));
    }
    __syncthreads();

    float acc[4][4];
    #pragma unroll
    for (int i = 0; i < 4; i++)
        #pragma unroll
        for (int j = 0; j < 4; j++) acc[i][j] = 0.f;

    #pragma unroll 8
    for (int p = 0; p < 64; p++) {
        float ra[4];
        *(float4*)ra = *(const float4*)&At[p][tx * 4];
        float rv[4];
        #pragma unroll
        for (int i = 0; i < 4; i++) rv[i] = Vs[ty * 4 + i][p];
        #pragma unroll
        for (int i = 0; i < 4; i++)
            #pragma unroll
            for (int j = 0; j < 4; j++)
                acc[i][j] = fmaf(rv[i], ra[j], acc[i][j]);
    }

    #pragma unroll
    for (int i = 0; i < 4; i++) {
        const size_t r = rowbase + ty * 4 + i;
        __half2 h0 = __floats2half2_rn(acc[i][0], acc[i][1]);
        __half2 h1 = __floats2half2_rn(acc[i][2], acc[i][3]);
        __half* op = g_oatth + r * Dd + h * dh + tx * 4;
        *(__half2*)(op)     = h0;
        *(__half2*)(op + 2) = h1;
    }
}

// ---------------------------------------------------------------------------
// host: tensormap construction via driver entry point (no -lcuda needed)
// ---------------------------------------------------------------------------
typedef CUresult (*EncodeTiledFn)(
    CUtensorMap*, CUtensorMapDataType, cuuint32_t, void*,
    const cuuint64_t*, const cuuint64_t*, const cuuint32_t*, const cuuint32_t*,
    CUtensorMapInterleave, CUtensorMapSwizzle, CUtensorMapL2promotion,
    CUtensorMapFloatOOBfill);

static void encode_map16(EncodeTiledFn enc, CUtensorMap* m, void* base,
                         unsigned long long cols, unsigned long long nrows,
                         unsigned boxrows)
{
    cuuint64_t dims[2]    = {cols, nrows};
    cuuint64_t strides[1] = {cols * 2};                // fp16
    cuuint32_t box[2]     = {64u, boxrows};            // 128B x boxrows
    cuuint32_t estr[2]    = {1u, 1u};
    enc(m, CU_TENSOR_MAP_DATA_TYPE_FLOAT16, 2, base, dims, strides, box, estr,
        CU_TENSOR_MAP_INTERLEAVE_NONE, CU_TENSOR_MAP_SWIZZLE_128B,
        CU_TENSOR_MAP_L2_PROMOTION_L2_128B, CU_TENSOR_MAP_FLOAT_OOB_FILL_NONE);
}

extern "C" void kernel_launch(void* const* d_in, const int* in_sizes, int n_in,
                              void* d_out, int out_size)
{
    const float* x     = (const float*)d_in[0];
    const float* Wqkv  = (const float*)d_in[1];
    const float* temp  = (const float*)d_in[2];
    const float* Wout  = (const float*)d_in[3];
    const float* bout  = (const float*)d_in[4];
    float* out = (float*)d_out;

    __half *xh, *wth, *woth, *oatth, *qkT, *vh;
    cudaGetSymbolAddress((void**)&xh,    g_xh);
    cudaGetSymbolAddress((void**)&wth,   g_wth);
    cudaGetSymbolAddress((void**)&woth,  g_woth);
    cudaGetSymbolAddress((void**)&oatth, g_oatth);
    cudaGetSymbolAddress((void**)&qkT,   g_qkT);
    cudaGetSymbolAddress((void**)&vh,    g_vh);
    CUtensorMap* dmaps;
    cudaGetSymbolAddress((void**)&dmaps, g_tmaps);

    static CUtensorMap h_tmaps[5];
    static EncodeTiledFn enc = nullptr;
    if (!enc) {
        void* p = nullptr;
        cudaDriverEntryPointQueryResult st;
        cudaGetDriverEntryPoint("cuTensorMapEncodeTiled", &p, cudaEnableDefault, &st);
        enc = (EncodeTiledFn)p;
    }
    encode_map16(enc, &h_tmaps[0], xh,    GK, (unsigned long long)Mrows, 256);
    encode_map16(enc, &h_tmaps[1], wth,   GK, (unsigned long long)QKVC, 128);
    encode_map16(enc, &h_tmaps[2], oatth, GK, (unsigned long long)Mrows, 256);
    encode_map16(enc, &h_tmaps[3], woth,  GK, (unsigned long long)Dd,   128);
    encode_map16(enc, &h_tmaps[4], qkT,   Nn, (unsigned long long)(Bc*Hh*128), 128);
    cudaMemcpyToSymbolAsync(g_tmaps, h_tmaps, sizeof(h_tmaps), 0,
                            cudaMemcpyHostToDevice, 0);

    cudaFuncSetAttribute(gemm_f16, cudaFuncAttributeMaxDynamicSharedMemorySize, GEMM_SMEM);
    cudaFuncSetAttribute(attn_tc,  cudaFuncAttributeMaxDynamicSharedMemorySize, ATTN_SMEM);

    // 1) x -> fp16; transpose weights -> fp16
    {
        size_t n4 = (size_t)Mrows * Dd / 4;
        half_kernel<<<(unsigned)((n4 + 255) / 256), 256>>>(x, xh, n4);
    }
    transpose_half<<<dim3(QKVC/32, Dd/32), 256>>>(Wqkv, wth, Dd, QKVC);
    transpose_half<<<dim3(Dd/32,  Dd/32), 256>>>(Wout, woth, Dd, Dd);

    // 2) qkv = x @ Wqkv; q,k transposed fp16 -> g_qkT (coalesced), v -> g_vh
    gemm_f16<<<dim3(QKVC/NT, Mrows/MT), 256, GEMM_SMEM>>>(
        dmaps + 0, xh, wth, nullptr, QKVC, nullptr, qkT, vh);

    // 3) attention via tcgen05: D = [k;q][k;q]^T -> norms + softmax
    attn_tc<<<dim3(Bc * Hh), 128, ATTN_SMEM>>>(dmaps + 4, temp);

    // 4) out = v @ attn  (fp16 in, fp16 out)
    av_kernel<<<dim3(Bc * Hh, Nn / 64), 256>>>();

    // 5) final projection + bias -> fp32 out
    gemm_f16<<<dim3(Dd/NT, Mrows/MT), 256, GEMM_SMEM>>>(
        dmaps + 2, oatth, woth, out, Dd, bout, nullptr, nullptr);
}

// round 17
// speedup vs baseline: 1.4758x; 1.0333x over previous
#include <cuda_runtime.h>
#include <cuda.h>
#include <cuda_fp16.h>
#include <math.h>
#include <stdint.h>

#define Bc 8
#define Nn 4096
#define Dd 768
#define Hh 12
#define dh 64
#define Mrows (Bc*Nn)      /* 32768 */
#define QKVC  (3*Dd)       /* 2304  */
#define GK    Dd           /* GEMM K = 768 */

// ---------------- scratch (device globals; allocation-free rule) -----------
__device__ float g_attn[Bc*Hh*dh*dh];                        // 1.5 MB
__device__ __align__(256) __half g_qkT[(size_t)Bc*Hh*128*Nn];  // 100 MB [bh][128][4096]
__device__ __align__(256) __half g_vh[(size_t)Mrows*Dd];       // 50 MB  v fp16
__device__ __align__(256) __half g_xh[(size_t)Mrows*Dd];       // x fp16
__device__ __align__(256) __half g_wth[(size_t)QKVC*Dd];       // Wqkv^T [N,K] fp16
__device__ __align__(256) __half g_w2t[(size_t)Bc*Dd*Dd];      // 9.4 MB (attn@Wout)^T per batch
// tensormaps: [0]=xh(A1), [1]=wth(B1), [2]=vh(A2), [3]=w2t(B2), [4]=qkT
__device__ __align__(128) CUtensorMap g_tmaps[5];

// ---------------- arch feature gate -----------------------------------------
#if defined(__CUDA_ARCH_FEAT_SM103_ALL) || defined(__CUDA_ARCH_FEAT_SM100_ALL) || defined(__CUDA_ARCH_FEAT_SM101_ALL)
#define HAS_TCG 1
#else
#define HAS_TCG 0
#endif

// ---------------- common helpers --------------------------------------------
__device__ __forceinline__ uint32_t smem_u32(const void* p){
    uint32_t a;
    asm("{ .reg .u64 t; cvta.to.shared.u64 t, %1; cvt.u32.u64 %0, t; }" : "=r"(a) : "l"(p));
    return a;
}

// ---------------- GEMM tile geometry (fp16) ----------------------------------
#define MT 256
#define NT 256
#define KCH 64                  /* K elems per chunk: 64 fp16 = 128B rows */
#define NCH (GK/KCH)            /* 12 */
#define NSTAGE 3
#define OA 0                    /* A tile 256x64 fp16 = 32KB (M halves +16K) */
#define OB 32768                /* B tile 256x64 fp16 = 32KB (mc halves +16K) */
#define STAGE_BYTES 65536
#define SM_TILE0 1024
#define GEMM_SMEM (SM_TILE0 + NSTAGE*STAGE_BYTES) /* 197632 */

// attn_tc geometry (fp16)
#define ACH 64                  /* n per chunk: 64 fp16 = 128B rows */
#define ANCH (Nn/ACH)           /* 64 */
#define ANST 6
#define ASTAGE_BYTES 16384      /* 128 rows x 128B */
#define ATTN_SMEM (SM_TILE0 + ANST*ASTAGE_BYTES)  /* 99328 */

#if HAS_TCG
// ---------------- tcgen05 / TMA helpers (arch-specific pass only) -----------
__device__ __forceinline__ uint32_t elect1(){
    uint32_t p;
    asm volatile("{\n\t.reg .pred p;\n\telect.sync _|p, 0xFFFFFFFF;\n\tselp.b32 %0, 1, 0, p;\n\t}" : "=r"(p));
    return p;
}
__device__ __forceinline__ uint32_t ctarank(){
    uint32_t r;
    asm("mov.u32 %0, %%cluster_ctarank;" : "=r"(r));
    return r;
}
// SW128 K-major descriptor: layout=2, version=1, SBO=64, LBO=1 (128B rows)
static constexpr uint64_t DESC_BASE_SW128 =
    (uint64_t(2) << 61) | (uint64_t(1) << 46) | (uint64_t(64) << 32) | (uint64_t(1) << 16);
#define MK128(a) (DESC_BASE_SW128 | ((uint64_t)((a) >> 4) & 0x3FFF))
// idesc fp16 (atype=btype=0), F32 accum (1<<4), M=128 (8<<24)
#define IDESC_N256 0x8400010u
#define IDESC_N128 0x8200010u

__device__ __forceinline__ void mma_f16_ss(uint32_t d, uint64_t a, uint64_t b,
                                           uint32_t idesc, uint32_t en){
    asm volatile(
        "{\n\t.reg .pred p;\n\tsetp.ne.u32 p, %3, 0;\n\t"
        "tcgen05.mma.cta_group::1.kind::f16 [%0], %1, %2, %4, {%5,%5,%5,%5}, p;\n\t}"
        :: "r"(d), "l"(a), "l"(b), "r"(en), "r"(idesc), "r"(0u) : "memory");
}
__device__ __forceinline__ void tc_commit(uint32_t mbar){
    asm volatile("tcgen05.commit.cta_group::1.mbarrier::arrive::one.shared::cluster.b64 [%0];"
                 :: "r"(mbar) : "memory");
}
__device__ __forceinline__ void tc_commit_mc(uint32_t mbar, uint16_t mask){
    asm volatile("tcgen05.commit.cta_group::1.mbarrier::arrive::one.shared::cluster.multicast::cluster.b64 [%0], %1;"
                 :: "r"(mbar), "h"(mask) : "memory");
}
__device__ __forceinline__ void mbar_init(uint32_t mbar, uint32_t cnt){
    asm volatile("mbarrier.init.shared.b64 [%0], %1;" :: "r"(mbar), "r"(cnt) : "memory");
}
__device__ __forceinline__ void mbar_wait(uint32_t mbar, uint32_t parity){
    asm volatile(
        "{\n\t.reg .pred P;\n\tWL_%=:\n\t"
        "mbarrier.try_wait.parity.acquire.cta.shared::cta.b64 P, [%0], %1, 0x989680;\n\t"
        "@P bra.uni WD_%=;\n\tbra.uni WL_%=;\n\tWD_%=:\n\t}"
        :: "r"(mbar), "r"(parity) : "memory");
}
__device__ __forceinline__ void mbar_wait_rlx(uint32_t mbar, uint32_t parity){
    asm volatile(
        "{\n\t.reg .pred P;\n\tWL_%=:\n\t"
        "mbarrier.try_wait.parity.relaxed.cta.shared::cta.b64 P, [%0], %1, 0x989680;\n\t"
        "@P bra.uni WD_%=;\n\tbra.uni WL_%=;\n\tWD_%=:\n\t}"
        :: "r"(mbar), "r"(parity) : "memory");
}
#define EXPECT_TX(mbar, bytes) \
    asm volatile("mbarrier.arrive.expect_tx.shared.b64 _, [%0], %1;" \
                 :: "r"(mbar), "r"((uint32_t)(bytes)) : "memory")
#define TMA2D(smem, map, x, y, mbar) \
    asm volatile("cp.async.bulk.tensor.2d.shared::cta.global.tile.mbarrier::complete_tx::bytes " \
                 "[%0], [%1, {%2, %3}], [%4];" \
                 :: "r"((uint32_t)(smem)), "l"(map), "r"((int)(x)), "r"((int)(y)), \
                    "r"((uint32_t)(mbar)) : "memory")
#define TMA2D_MC(smem, map, x, y, mbar, mask) \
    asm volatile("cp.async.bulk.tensor.2d.shared::cluster.global.tile.mbarrier::complete_tx::bytes.multicast::cluster " \
                 "[%0], [%1, {%2, %3}], [%4], %5;" \
                 :: "r"((uint32_t)(smem)), "l"(map), "r"((int)(x)), "r"((int)(y)), \
                    "r"((uint32_t)(mbar)), "h"((uint16_t)(mask)) : "memory")
#define CLUSTER_SYNC() do { \
    asm volatile("barrier.cluster.arrive.aligned;" ::: "memory"); \
    asm volatile("barrier.cluster.wait.aligned;" ::: "memory"); \
} while(0)

#define TC_FENCE_AFTER()  asm volatile("tcgen05.fence::after_thread_sync;" ::: "memory")
#define TC_FENCE_BEFORE() asm volatile("tcgen05.fence::before_thread_sync;" ::: "memory")
#define TC_WAIT_LD() asm volatile("tcgen05.wait::ld.sync.aligned;" ::: "memory")

#define LDTM32(r, addr) \
    asm volatile( \
        "tcgen05.ld.sync.aligned.32x32b.x32.b32 " \
        "{%0, %1, %2, %3, %4, %5, %6, %7, " \
        " %8, %9, %10, %11, %12, %13, %14, %15, " \
        " %16, %17, %18, %19, %20, %21, %22, %23, " \
        " %24, %25, %26, %27, %28, %29, %30, %31}, [%32];" \
        : "=r"((r)[0]),  "=r"((r)[1]),  "=r"((r)[2]),  "=r"((r)[3]), \
          "=r"((r)[4]),  "=r"((r)[5]),  "=r"((r)[6]),  "=r"((r)[7]), \
          "=r"((r)[8]),  "=r"((r)[9]),  "=r"((r)[10]), "=r"((r)[11]), \
          "=r"((r)[12]), "=r"((r)[13]), "=r"((r)[14]), "=r"((r)[15]), \
          "=r"((r)[16]), "=r"((r)[17]), "=r"((r)[18]), "=r"((r)[19]), \
          "=r"((r)[20]), "=r"((r)[21]), "=r"((r)[22]), "=r"((r)[23]), \
          "=r"((r)[24]), "=r"((r)[25]), "=r"((r)[26]), "=r"((r)[27]), \
          "=r"((r)[28]), "=r"((r)[29]), "=r"((r)[30]), "=r"((r)[31]) \
        : "r"(addr))
#endif  // HAS_TCG

// smem control offsets
#define MB_FULL(s)  (8  + (s)*8)
#define MB_EMPTY(s) (64 + (s)*8)
#define MB_DONE     120
#define SO_NORM     256              /* attn_tc: float norm[128] at +256 */

// ---------------------------------------------------------------------------
// fp16 tcgen05 GEMM:  C = A[M,GK] * B^T  (A,B fp16 K-major row-major)
// GEMM1 mode (qkT/vh non-null): q,k transposed via SMEM-staged coalesced
// stores; v written fp16 row-major. GEMM2 mode: fp32 C + bias, B batched
// by bstride (B row = (r>>12)*bstride + c).
// ---------------------------------------------------------------------------
__global__ __launch_bounds__(256) __cluster_dims__(1, 2, 1)
void gemm_f16(
    const CUtensorMap* __restrict__ tmaps,   // [A, B]
    const __half* __restrict__ A, const __half* __restrict__ B,
    float* __restrict__ C, int Ntot, const float* __restrict__ bias,
    __half* __restrict__ qkT, __half* __restrict__ vh, int bstride)
{
    const int tid = threadIdx.x;
    const int row0 = blockIdx.y * MT;
    const int col0 = blockIdx.x * NT;

#if HAS_TCG
    extern __shared__ char smem[];
    const uint32_t sbase = smem_u32(smem);
    const int wid = tid >> 5;
    const int lane = tid & 31;
    const uint32_t rank = ctarank();

    if (wid == 0) {
        asm volatile("tcgen05.alloc.cta_group::1.sync.aligned.shared::cta.b32 [%0], %1;"
                     :: "r"(sbase), "r"(512u) : "memory");
    }
    if (tid == 0) {
        #pragma unroll
        for (int s = 0; s < NSTAGE; s++) {
            mbar_init(sbase + MB_FULL(s), 1);
            mbar_init(sbase + MB_EMPTY(s), 2);
        }
        mbar_init(sbase + MB_DONE, 1);
    }
    __syncthreads();
    uint32_t tmem;
    asm volatile("ld.shared.b32 %0, [%1];" : "=r"(tmem) : "r"(sbase));
    if (wid == 0)
        asm volatile("tcgen05.relinquish_alloc_permit.cta_group::1.sync.aligned;");

    CLUSTER_SYNC();

    uint32_t leader = 0, producer = 0;
    if (wid == 0) leader = elect1();
    if (wid == 1) producer = elect1();

    if (producer) {
        const int ybbase = (row0 >> 12) * bstride + col0 + (int)rank*128;
        for (int ch = 0; ch < NCH; ch++) {
            const int st = ch % NSTAGE;
            const uint32_t sb = sbase + SM_TILE0 + st*STAGE_BYTES;
            if (ch >= NSTAGE)
                mbar_wait_rlx(sbase + MB_EMPTY(st), ((ch - NSTAGE) / NSTAGE) & 1);
            EXPECT_TX(sbase + MB_FULL(st), 65536u);
            TMA2D(sb + OA, tmaps + 0, ch*KCH, row0, sbase + MB_FULL(st));
            TMA2D_MC(sb + OB + rank*16384, tmaps + 1, ch*KCH,
                     ybbase, sbase + MB_FULL(st), 3);
        }
    }

    if (leader) {
        uint32_t first = 0;
        const uint32_t tm0 = tmem, tm1 = tmem + 256;
        for (int ch = 0; ch < NCH; ch++) {
            const int st = ch % NSTAGE;
            mbar_wait(sbase + MB_FULL(st), (ch / NSTAGE) & 1);
            const uint32_t sb = sbase + SM_TILE0 + st*STAGE_BYTES;
            const uint64_t dA0 = MK128(sb + OA);
            const uint64_t dA1 = MK128(sb + OA + 16384);
            const uint64_t dB  = MK128(sb + OB);
            #pragma unroll
            for (int k = 0; k < 4; k++) {      // K=16 per f16 MMA; 4 k-steps
                const uint64_t o = k*2;        // 32B per k-step
                mma_f16_ss(tm0, dA0 + o, dB + o, IDESC_N256, first);
                mma_f16_ss(tm1, dA1 + o, dB + o, IDESC_N256, first);
                first = 1;
            }
            tc_commit_mc(sbase + MB_EMPTY(st), 3);
        }
        tc_commit(sbase + MB_DONE);
    }

    mbar_wait(sbase + MB_DONE, 0);
    TC_FENCE_AFTER();

    // ---- epilogue ----
    {
        const int mh = wid >> 2;
        const int rr = mh*128 + (wid & 3)*32 + lane;   // CTA-local row 0..255
        const int r  = row0 + rr;
        const uint32_t tb = tmem + mh*256;
        const bool g1 = (qkT != nullptr);

        if (g1 && col0 < 1536) {
            // q/k tile: SMEM-staged transpose, coalesced STG.128 writes.
            __half* sT = (__half*)(smem + SM_TILE0);
            const int bb2 = row0 >> 12;
            const int n0v = row0 & 4095;
            #pragma unroll
            for (int chk = 0; chk < 8; chk++) {
                uint32_t regs[32];
                LDTM32(regs, tb + chk*32);
                TC_WAIT_LD();
                #pragma unroll
                for (int j = 0; j < 32; j++)
                    sT[j*264 + rr] = __float2half_rn(__uint_as_float(regs[j]));
                __syncthreads();
                #pragma unroll
                for (int it = 0; it < 4; it++) {
                    const int col = it*8 + wid;
                    const int c = col0 + chk*32 + col;
                    const int cc = (c < 768) ? c : c - 768;
                    const int qrow = (bb2*Hh + (cc >> 6))*128
                                     + ((c < 768) ? 64 : 0) + (cc & 63);
                    float4 val = *(float4*)&sT[col*264 + lane*8];
                    *(float4*)(qkT + (size_t)qrow * Nn + n0v + lane*8) = val;
                }
                __syncthreads();
            }
        } else if (g1) {
            // v tile -> fp16 row-major [Mrows x 768]
            #pragma unroll
            for (int chk = 0; chk < 8; chk++) {
                uint32_t regs[32];
                LDTM32(regs, tb + chk*32);
                TC_WAIT_LD();
                const int c0 = col0 + chk*32;
                __half* vrow = vh + (size_t)r * Dd + (c0 - 1536);
                #pragma unroll
                for (int j = 0; j < 32; j += 2) {
                    __half2 hv = __floats2half2_rn(
                        __uint_as_float(regs[j]), __uint_as_float(regs[j+1]));
                    *(__half2*)(vrow + j) = hv;
                }
            }
        } else {
            float* crow = C + (size_t)r * Ntot;
            #pragma unroll
            for (int chk = 0; chk < 8; chk++) {
                uint32_t regs[32];
                LDTM32(regs, tb + chk*32);
                TC_WAIT_LD();
                const int c0 = col0 + chk*32;
                #pragma unroll
                for (int j = 0; j < 32; j += 4) {
                    float4 v;
                    v.x = __uint_as_float(regs[j+0]);
                    v.y = __uint_as_float(regs[j+1]);
                    v.z = __uint_as_float(regs[j+2]);
                    v.w = __uint_as_float(regs[j+3]);
                    if (bias) {
                        v.x += bias[c0+j+0]; v.y += bias[c0+j+1];
                        v.z += bias[c0+j+2]; v.w += bias[c0+j+3];
                    }
                    *(float4*)(crow + c0 + j) = v;
                }
            }
        }
        TC_FENCE_BEFORE();
    }
    __syncthreads();
    CLUSTER_SYNC();
    if (tid == 0) {
        #pragma unroll
        for (int s = 0; s < NSTAGE; s++) {
            asm volatile("mbarrier.inval.shared.b64 [%0];" :: "r"(sbase + MB_FULL(s)) : "memory");
            asm volatile("mbarrier.inval.shared.b64 [%0];" :: "r"(sbase + MB_EMPTY(s)) : "memory");
        }
        asm volatile("mbarrier.inval.shared.b64 [%0];" :: "r"(sbase + MB_DONE) : "memory");
    }
    __syncthreads();
    if (wid == 0) {
        asm volatile("tcgen05.dealloc.cta_group::1.sync.aligned.b32 %0, %1;"
                     :: "r"(tmem), "r"(512u));
    }
    CLUSTER_SYNC();

#else
    (void)tmaps;
    for (int idx = tid; idx < MT*NT; idx += 256) {
        const int r = row0 + idx / NT;
        const int c = col0 + idx % NT;
        const int brow = (r >> 12) * bstride + c;
        float s = bias ? bias[c] : 0.f;
        for (int k = 0; k < GK; k++)
            s = fmaf(__half2float(A[(size_t)r * GK + k]),
                     __half2float(B[(size_t)brow * GK + k]), s);
        if (qkT) {
            if (c < 1536) {
                const int bb = r >> 12, nn = r & 4095;
                const int cc = (c < 768) ? c : c - 768;
                const int qrow = (bb*Hh + (cc >> 6))*128 + ((c < 768) ? 64 : 0) + (cc & 63);
                qkT[(size_t)qrow * Nn + nn] = __float2half_rn(s);
            } else {
                vh[(size_t)r * Dd + (c - 1536)] = __float2half_rn(s);
            }
        } else {
            C[(size_t)r * Ntot + c] = s;
        }
    }
#endif
}

// ---------------------------------------------------------------------------
// attn_tc: per (b,h), D[128x128] = T T^T over n (T = [k;q] fp16, 128 x 4096),
// then norms from diag, temperature, softmax -> g_attn. grid 96, block 128.
// ---------------------------------------------------------------------------
__global__ __launch_bounds__(128) void attn_tc(
    const CUtensorMap* __restrict__ tmap, const float* __restrict__ temp)
{
    const int bh = blockIdx.x;
    const int tid = threadIdx.x;

#if HAS_TCG
    extern __shared__ char smem[];
    const uint32_t sbase = smem_u32(smem);
    const int wid = tid >> 5;
    const int lane = tid & 31;

    if (wid == 0) {
        asm volatile("tcgen05.alloc.cta_group::1.sync.aligned.shared::cta.b32 [%0], %1;"
                     :: "r"(sbase), "r"(128u) : "memory");
    }
    if (tid == 0) {
        #pragma unroll
        for (int s = 0; s < ANST; s++) {
            mbar_init(sbase + MB_FULL(s), 1);
            mbar_init(sbase + MB_EMPTY(s), 1);
        }
        mbar_init(sbase + MB_DONE, 1);
    }
    __syncthreads();
    uint32_t tmem;
    asm volatile("ld.shared.b32 %0, [%1];" : "=r"(tmem) : "r"(sbase));
    if (wid == 0)
        asm volatile("tcgen05.relinquish_alloc_permit.cta_group::1.sync.aligned;");
    __syncthreads();

    uint32_t leader = 0, producer = 0;
    if (wid == 0) leader = elect1();
    if (wid == 1) producer = elect1();

    if (producer) {
        for (int ch = 0; ch < ANCH; ch++) {
            const int st = ch % ANST;
            const uint32_t sb = sbase + SM_TILE0 + st*ASTAGE_BYTES;
            if (ch >= ANST)
                mbar_wait_rlx(sbase + MB_EMPTY(st), ((ch - ANST) / ANST) & 1);
            EXPECT_TX(sbase + MB_FULL(st), 16384u);
            TMA2D(sb, tmap, ch*ACH, bh*128, sbase + MB_FULL(st));
        }
    }

    if (leader) {
        uint32_t first = 0;
        for (int ch = 0; ch < ANCH; ch++) {
            const int st = ch % ANST;
            mbar_wait(sbase + MB_FULL(st), (ch / ANST) & 1);
            const uint64_t dT = MK128(sbase + SM_TILE0 + st*ASTAGE_BYTES);
            #pragma unroll
            for (int k = 0; k < 4; k++) {
                mma_f16_ss(tmem, dT + k*2, dT + k*2, IDESC_N128, first);
                first = 1;
            }
            tc_commit(sbase + MB_EMPTY(st));
        }
        tc_commit(sbase + MB_DONE);
    }

    mbar_wait(sbase + MB_DONE, 0);
    TC_FENCE_AFTER();

    {
        const int r = wid*32 + lane;
        uint32_t regs[128];
        #pragma unroll
        for (int chk = 0; chk < 4; chk++) {
            LDTM32(regs + chk*32, tmem + chk*32);
        }
        TC_WAIT_LD();
        TC_FENCE_BEFORE();

        float* normp = (float*)(smem + SO_NORM);
        normp[r] = fmaxf(sqrtf(__uint_as_float(regs[r])), 1e-12f);
        __syncthreads();

        if (r < 64) {
            const float tv = temp[bh % Hh];
            const float nk = normp[r];
            float vals[64];
            float m = -1e30f;
            #pragma unroll
            for (int q = 0; q < 64; q++) {
                vals[q] = __uint_as_float(regs[64+q]) * tv / (nk * normp[64+q]);
                m = fmaxf(m, vals[q]);
            }
            float s = 0.f;
            #pragma unroll
            for (int q = 0; q < 64; q++) { vals[q] = expf(vals[q] - m); s += vals[q]; }
            const float inv = 1.f / s;
            float* op = g_attn + (size_t)bh * 4096 + r * 64;
            #pragma unroll
            for (int q = 0; q < 64; q += 4) {
                float4 v;
                v.x = vals[q+0]*inv; v.y = vals[q+1]*inv;
                v.z = vals[q+2]*inv; v.w = vals[q+3]*inv;
                *(float4*)(op + q) = v;
            }
        }
    }
    __syncthreads();
    if (tid == 0) {
        #pragma unroll
        for (int s = 0; s < ANST; s++) {
            asm volatile("mbarrier.inval.shared.b64 [%0];" :: "r"(sbase + MB_FULL(s)) : "memory");
            asm volatile("mbarrier.inval.shared.b64 [%0];" :: "r"(sbase + MB_EMPTY(s)) : "memory");
        }
        asm volatile("mbarrier.inval.shared.b64 [%0];" :: "r"(sbase + MB_DONE) : "memory");
    }
    __syncthreads();
    if (wid == 0) {
        asm volatile("tcgen05.dealloc.cta_group::1.sync.aligned.b32 %0, %1;"
                     :: "r"(tmem), "r"(128u));
    }

#else
    (void)tmap;
    if (tid == 0) {
        const float tv = temp[bh % Hh];
        const __half* T = g_qkT + (size_t)bh * 128 * Nn;
        float normv[128];
        for (int i = 0; i < 128; i++) {
            double s = 0;
            for (int n = 0; n < Nn; n++) {
                float v = __half2float(T[(size_t)i*Nn+n]); s += (double)v*v;
            }
            normv[i] = fmaxf(sqrtf((float)s), 1e-12f);
        }
        for (int p = 0; p < 64; p++) {
            float vals[64]; float m = -1e30f;
            for (int q = 0; q < 64; q++) {
                double s = 0;
                for (int n = 0; n < Nn; n++)
                    s += (double)__half2float(T[(size_t)p*Nn+n]) *
                         (double)__half2float(T[(size_t)(64+q)*Nn+n]);
                vals[q] = (float)s * tv / (normv[p] * normv[64+q]);
                m = fmaxf(m, vals[q]);
            }
            float s = 0;
            for (int q = 0; q < 64; q++) { vals[q] = expf(vals[q]-m); s += vals[q]; }
            for (int q = 0; q < 64; q++)
                g_attn[(size_t)bh*4096 + p*64 + q] = vals[q] / s;
        }
    }
#endif
}

// ---------------------------------------------------------------------------
// w2_kernel: W2T[b][c][h*64+p] = sum_q attn[b,h,p,q] * Wout[h*64+q][c], fp16.
// grid 96 (bh), block 256. Deletes the av pass algebraically.
// ---------------------------------------------------------------------------
__global__ __launch_bounds__(256) void w2_kernel(const float* __restrict__ Wout)
{
    const int bh = blockIdx.x;
    const int b = bh / Hh, h = bh % Hh;
    const int tid = threadIdx.x;

    __shared__ float As[64][65];   // attn[p][q]
    __shared__ float Ws[64][65];   // Wout[h*64+q][ct*64+c]

    for (int idx = tid; idx < 4096; idx += 256)
        As[idx >> 6][idx & 63] = g_attn[(size_t)bh * 4096 + idx];

    const int p = tid & 63;
    const int cbase = (tid >> 6) * 16;   // 0,16,32,48

    for (int ct = 0; ct < 12; ct++) {
        __syncthreads();
        for (int idx = tid; idx < 4096; idx += 256) {
            const int q = idx >> 6, c = idx & 63;
            Ws[q][c] = Wout[(size_t)(h*64 + q) * Dd + ct*64 + c];
        }
        __syncthreads();
        #pragma unroll 4
        for (int cc = 0; cc < 16; cc++) {
            const int c = cbase + cc;
            float acc = 0.f;
            #pragma unroll
            for (int q = 0; q < 64; q++)
                acc = fmaf(As[p][q], Ws[q][c], acc);
            g_w2t[((size_t)b*Dd + ct*64 + c) * Dd + h*64 + p] = __float2half_rn(acc);
        }
    }
}

// ---------------------------------------------------------------------------
// fp32 -> fp16 (elementwise, rn)
// ---------------------------------------------------------------------------
__global__ __launch_bounds__(256) void half_kernel(
    const float* __restrict__ in, __half* __restrict__ outp, size_t n4)
{
    const size_t i = (size_t)blockIdx.x * blockDim.x + threadIdx.x;
    if (i >= n4) return;
    float4 v = ((const float4*)in)[i];
    __half2 h0 = __floats2half2_rn(v.x, v.y);
    __half2 h1 = __floats2half2_rn(v.z, v.w);
    ((__half2*)outp)[2*i]   = h0;
    ((__half2*)outp)[2*i+1] = h1;
}

// ---------------------------------------------------------------------------
// W [K,N] fp32 -> transposed fp16 [N,K] row-major
// ---------------------------------------------------------------------------
__global__ __launch_bounds__(256) void transpose_half(
    const float* __restrict__ W, __half* __restrict__ o, int K, int N)
{
    __shared__ float t[32][33];
    const int n0 = blockIdx.x * 32, k0 = blockIdx.y * 32;
    const int tx = threadIdx.x & 31, ty = threadIdx.x >> 5;
    #pragma unroll
    for (int i = ty; i < 32; i += 8)
        t[i][tx] = W[(size_t)(k0 + i) * N + n0 + tx];
    __syncthreads();
    #pragma unroll
    for (int i = ty; i < 32; i += 8)
        o[(size_t)(n0 + i) * K + k0 + tx] = __float2half_rn(t[tx][i]);
}

// ---------------------------------------------------------------------------
// host: tensormap construction via driver entry point (no -lcuda needed)
// ---------------------------------------------------------------------------
typedef CUresult (*EncodeTiledFn)(
    CUtensorMap*, CUtensorMapDataType, cuuint32_t, void*,
    const cuuint64_t*, const cuuint64_t*, const cuuint32_t*, const cuuint32_t*,
    CUtensorMapInterleave, CUtensorMapSwizzle, CUtensorMapL2promotion,
    CUtensorMapFloatOOBfill);

static void encode_map16(EncodeTiledFn enc, CUtensorMap* m, void* base,
                         unsigned long long cols, unsigned long long nrows,
                         unsigned boxrows)
{
    cuuint64_t dims[2]    = {cols, nrows};
    cuuint64_t strides[1] = {cols * 2};                // fp16
    cuuint32_t box[2]     = {64u, boxrows};            // 128B x boxrows
    cuuint32_t estr[2]    = {1u, 1u};
    enc(m, CU_TENSOR_MAP_DATA_TYPE_FLOAT16, 2, base, dims, strides, box, estr,
        CU_TENSOR_MAP_INTERLEAVE_NONE, CU_TENSOR_MAP_SWIZZLE_128B,
        CU_TENSOR_MAP_L2_PROMOTION_L2_128B, CU_TENSOR_MAP_FLOAT_OOB_FILL_NONE);
}

extern "C" void kernel_launch(void* const* d_in, const int* in_sizes, int n_in,
                              void* d_out, int out_size)
{
    const float* x     = (const float*)d_in[0];
    const float* Wqkv  = (const float*)d_in[1];
    const float* temp  = (const float*)d_in[2];
    const float* Wout  = (const float*)d_in[3];
    const float* bout  = (const float*)d_in[4];
    float* out = (float*)d_out;

    __half *xh, *wth, *qkT, *vh, *w2t;
    cudaGetSymbolAddress((void**)&xh,   g_xh);
    cudaGetSymbolAddress((void**)&wth,  g_wth);
    cudaGetSymbolAddress((void**)&qkT,  g_qkT);
    cudaGetSymbolAddress((void**)&vh,   g_vh);
    cudaGetSymbolAddress((void**)&w2t,  g_w2t);
    CUtensorMap* dmaps;
    cudaGetSymbolAddress((void**)&dmaps, g_tmaps);

    static CUtensorMap h_tmaps[5];
    static EncodeTiledFn enc = nullptr;
    if (!enc) {
        void* p = nullptr;
        cudaDriverEntryPointQueryResult st;
        cudaGetDriverEntryPoint("cuTensorMapEncodeTiled", &p, cudaEnableDefault, &st);
        enc = (EncodeTiledFn)p;
    }
    encode_map16(enc, &h_tmaps[0], xh,  GK, (unsigned long long)Mrows, 256);
    encode_map16(enc, &h_tmaps[1], wth, GK, (unsigned long long)QKVC, 128);
    encode_map16(enc, &h_tmaps[2], vh,  GK, (unsigned long long)Mrows, 256);
    encode_map16(enc, &h_tmaps[3], w2t, GK, (unsigned long long)(Bc*Dd), 128);
    encode_map16(enc, &h_tmaps[4], qkT, Nn, (unsigned long long)(Bc*Hh*128), 128);
    cudaMemcpyToSymbolAsync(g_tmaps, h_tmaps, sizeof(h_tmaps), 0,
                            cudaMemcpyHostToDevice, 0);

    cudaFuncSetAttribute(gemm_f16, cudaFuncAttributeMaxDynamicSharedMemorySize, GEMM_SMEM);
    cudaFuncSetAttribute(attn_tc,  cudaFuncAttributeMaxDynamicSharedMemorySize, ATTN_SMEM);

    // 1) x -> fp16; transpose Wqkv -> fp16
    {
        size_t n4 = (size_t)Mrows * Dd / 4;
        half_kernel<<<(unsigned)((n4 + 255) / 256), 256>>>(x, xh, n4);
    }
    transpose_half<<<dim3(QKVC/32, Dd/32), 256>>>(Wqkv, wth, Dd, QKVC);

    // 2) qkv = x @ Wqkv; q,k transposed fp16 -> g_qkT, v fp16 -> g_vh
    gemm_f16<<<dim3(QKVC/NT, Mrows/MT), 256, GEMM_SMEM>>>(
        dmaps + 0, xh, wth, nullptr, QKVC, nullptr, qkT, vh, 0);

    // 3) attention via tcgen05: D = [k;q][k;q]^T -> norms + softmax
    attn_tc<<<dim3(Bc * Hh), 128, ATTN_SMEM>>>(dmaps + 4, temp);

    // 4) W2T[b] = (blockdiag(attn_b) @ Wout)^T  (fp16)
    w2_kernel<<<dim3(Bc * Hh), 256>>>(Wout);

    // 5) out = v @ W2[b] + bias  (batched B via bstride=768)
    gemm_f16<<<dim3(Dd/NT, Mrows/MT), 256, GEMM_SMEM>>>(
        dmaps + 2, vh, w2t, out, Dd, bout, nullptr, nullptr, Dd);
}